// round 2
// baseline (speedup 1.0000x reference)
#include <cuda_runtime.h>
#include <cuda_bf16.h>

#define B_  16
#define C_  256
#define S_  64
#define H_  8
#define D_  32
#define HD_ 256
#define P_  4096

// scratch (device globals; allocations are forbidden)
__device__ float g_convv[(size_t)B_*C_*P_];      // [b][c][p] channel-major
__device__ float g_pool[4][B_*S_*C_];            // [path][b*64+pos][c]
__device__ float g_qk[4][B_*S_*HD_];             // [path][b*64+pos][hd]
__device__ float g_attn[2][B_*H_*S_*S_];         // [axis][bh][i][j]
__device__ float g_vlin[(size_t)B_*P_*HD_];      // [b][p][hd]
__device__ float g_M[(size_t)B_*H_*D_*S_*S_];    // [bh][dv][i][w]
__device__ float g_r[(size_t)B_*HD_*P_];         // [b][hd][p]

// ---- kernel 1: fused 5x depthwise 3x3 conv + row/col means -----------------
__global__ void __launch_bounds__(256) conv5_kernel(
    const float* __restrict__ x,
    const float* __restrict__ w_qh, const float* __restrict__ b_qh,
    const float* __restrict__ w_kh, const float* __restrict__ b_kh,
    const float* __restrict__ w_v,  const float* __restrict__ b_v,
    const float* __restrict__ w_qw, const float* __restrict__ b_qw,
    const float* __restrict__ w_kw, const float* __restrict__ b_kw)
{
    __shared__ float tile[66*66];
    __shared__ float s_row[2][64];
    __shared__ float s_colbuf[2][256];

    int b = blockIdx.x >> 8;
    int c = blockIdx.x & 255;
    int tid = threadIdx.x;

    const float* xp = x + (size_t)(b*C_ + c) * P_;
    for (int idx = tid; idx < 66*66; idx += 256) {
        int r = idx / 66 - 1, cc = idx % 66 - 1;
        float v = 0.f;
        if ((unsigned)r < 64u && (unsigned)cc < 64u) v = xp[r*64 + cc];
        tile[idx] = v;
    }
    if (tid < 64) { s_row[0][tid] = 0.f; s_row[1][tid] = 0.f; }

    float wqh[9], wkh[9], wv[9], wqw[9], wkw[9];
    #pragma unroll
    for (int k = 0; k < 9; k++) {
        wqh[k] = w_qh[c*9+k]; wkh[k] = w_kh[c*9+k]; wv[k] = w_v[c*9+k];
        wqw[k] = w_qw[c*9+k]; wkw[k] = w_kw[c*9+k];
    }
    float bqh = b_qh[c], bkh = b_kh[c], bv = b_v[c], bqw = b_qw[c], bkw = b_kw[c];
    __syncthreads();

    float acc_qw = 0.f, acc_kw = 0.f;
    int col = tid & 63;
    float* outv = g_convv + (size_t)(b*C_ + c) * P_;

    #pragma unroll 4
    for (int it = 0; it < 16; it++) {
        int p = it*256 + tid;
        int r = p >> 6;
        float n[9];
        #pragma unroll
        for (int dr = 0; dr < 3; dr++)
            #pragma unroll
            for (int dc = 0; dc < 3; dc++)
                n[dr*3+dc] = tile[(r+dr)*66 + col + dc];
        float sv = bv, sqh = bqh, skh = bkh, sqw = bqw, skw = bkw;
        #pragma unroll
        for (int k = 0; k < 9; k++) {
            sv  += wv[k]  * n[k];
            sqh += wqh[k] * n[k];
            skh += wkh[k] * n[k];
            sqw += wqw[k] * n[k];
            skw += wkw[k] * n[k];
        }
        outv[p] = sv;
        acc_qw += sqw; acc_kw += skw;
        float rq = sqh, rk = skh;   // whole warp shares row r
        #pragma unroll
        for (int o = 16; o; o >>= 1) {
            rq += __shfl_down_sync(0xffffffffu, rq, o);
            rk += __shfl_down_sync(0xffffffffu, rk, o);
        }
        if ((tid & 31) == 0) { atomicAdd(&s_row[0][r], rq); atomicAdd(&s_row[1][r], rk); }
    }
    s_colbuf[0][tid] = acc_qw;
    s_colbuf[1][tid] = acc_kw;
    __syncthreads();

    if (tid < 64) {
        float cq = s_colbuf[0][tid] + s_colbuf[0][tid+64] + s_colbuf[0][tid+128] + s_colbuf[0][tid+192];
        float ck = s_colbuf[1][tid] + s_colbuf[1][tid+64] + s_colbuf[1][tid+128] + s_colbuf[1][tid+192];
        size_t o = (size_t)(b*64 + tid) * C_ + c;
        const float inv = 1.f / 64.f;
        g_pool[0][o] = s_row[0][tid] * inv;
        g_pool[1][o] = s_row[1][tid] * inv;
        g_pool[2][o] = cq * inv;
        g_pool[3][o] = ck * inv;
    }
}

// ---- kernel 2: small linear, row-major A [M,K], torch W[N,K] ---------------
__global__ void __launch_bounds__(256) linear_rm_kernel(
    const float* __restrict__ A, const float* __restrict__ W,
    const float* __restrict__ bias, float* __restrict__ out, int K, int Nstride)
{
    __shared__ float As[16][64];
    __shared__ float Ws[16][64];
    int tid = threadIdx.x;
    int m0 = blockIdx.x * 64, n0 = blockIdx.y * 64;
    int tx = tid & 15, ty = tid >> 4;
    int l_r = tid >> 2;
    int l_k = (tid & 3) * 4;
    float acc[4][4];
    #pragma unroll
    for (int i = 0; i < 4; i++)
        #pragma unroll
        for (int j = 0; j < 4; j++) acc[i][j] = 0.f;

    for (int k0 = 0; k0 < K; k0 += 16) {
        float4 av = *(const float4*)(A + (size_t)(m0 + l_r) * K + k0 + l_k);
        float4 wv = *(const float4*)(W + (size_t)(n0 + l_r) * K + k0 + l_k);
        __syncthreads();
        As[l_k+0][l_r] = av.x; As[l_k+1][l_r] = av.y; As[l_k+2][l_r] = av.z; As[l_k+3][l_r] = av.w;
        Ws[l_k+0][l_r] = wv.x; Ws[l_k+1][l_r] = wv.y; Ws[l_k+2][l_r] = wv.z; Ws[l_k+3][l_r] = wv.w;
        __syncthreads();
        #pragma unroll
        for (int kk = 0; kk < 16; kk++) {
            float a[4], bb[4];
            *(float4*)a  = *(const float4*)&As[kk][ty*4];
            *(float4*)bb = *(const float4*)&Ws[kk][tx*4];
            #pragma unroll
            for (int i = 0; i < 4; i++)
                #pragma unroll
                for (int j = 0; j < 4; j++) acc[i][j] += a[i] * bb[j];
        }
    }
    float bs[4];
    #pragma unroll
    for (int j = 0; j < 4; j++) bs[j] = bias[n0 + tx*4 + j];
    #pragma unroll
    for (int i = 0; i < 4; i++) {
        float4 o;
        o.x = acc[i][0] + bs[0]; o.y = acc[i][1] + bs[1];
        o.z = acc[i][2] + bs[2]; o.w = acc[i][3] + bs[3];
        *(float4*)(out + (size_t)(m0 + ty*4 + i) * Nstride + n0 + tx*4) = o;
    }
}

// ---- kernel 3: attention logits + softmax -----------------------------------
__global__ void __launch_bounds__(256) attn_kernel(const float* __restrict__ Bh,
                                                   const float* __restrict__ Bw)
{
    __shared__ float Qs[64*33];
    __shared__ float Ks[64*33];
    __shared__ float L[64*65];
    int tid = threadIdx.x;
    int path = blockIdx.x >> 7;
    int bh = blockIdx.x & 127;
    int b = bh >> 3, Hh = bh & 7;

    const float* qg = g_qk[path*2]   + (size_t)(b*64) * 256 + Hh*32;
    const float* kg = g_qk[path*2+1] + (size_t)(b*64) * 256 + Hh*32;
    const float* bias = (path ? Bw : Bh) + (size_t)Hh * 4096;

    for (int e = tid; e < 2048; e += 256) {
        int i = e >> 5, d = e & 31;
        Qs[i*33+d] = qg[(size_t)i*256 + d];
        Ks[i*33+d] = kg[(size_t)i*256 + d];
    }
    __syncthreads();
    const float scale = 0.17677669529663687f;
    for (int e = tid; e < 4096; e += 256) {
        int i = e >> 6, j = e & 63;
        float s = 0.f;
        #pragma unroll
        for (int d = 0; d < 32; d++) s += Qs[i*33+d] * Ks[j*33+d];
        L[i*65+j] = s * scale + bias[i*64 + j];
    }
    __syncthreads();
    int warp = tid >> 5, lane = tid & 31;
    float* outp = g_attn[path] + (size_t)bh * 4096;
    for (int r = warp; r < 64; r += 8) {
        float v0 = L[r*65 + lane], v1 = L[r*65 + 32 + lane];
        float mx = fmaxf(v0, v1);
        #pragma unroll
        for (int o = 16; o; o >>= 1) mx = fmaxf(mx, __shfl_xor_sync(0xffffffffu, mx, o));
        float e0 = __expf(v0 - mx), e1 = __expf(v1 - mx);
        float s = e0 + e1;
        #pragma unroll
        for (int o = 16; o; o >>= 1) s += __shfl_xor_sync(0xffffffffu, s, o);
        float inv = 1.f / s;
        outp[r*64 + lane]      = e0 * inv;
        outp[r*64 + 32 + lane] = e1 * inv;
    }
}

// ---- kernel 4/7: big linear, A channel-major [b][k][p], out [b][p][n] -------
__global__ void __launch_bounds__(256) linear_cm_kernel(
    const float* __restrict__ Acm, const float* __restrict__ W,
    const float* __restrict__ bias, float* __restrict__ out)
{
    __shared__ float As[8][128];
    __shared__ float Ws[8][128];
    int tid = threadIdx.x;
    int bm = blockIdx.x;
    int n0 = blockIdx.y * 128;
    int b  = bm >> 5;
    int p0 = (bm & 31) * 128;
    const float* Ab = Acm + (size_t)b * C_ * P_ + p0;

    float acc[8][8];
    #pragma unroll
    for (int i = 0; i < 8; i++)
        #pragma unroll
        for (int j = 0; j < 8; j++) acc[i][j] = 0.f;

    int tx = tid & 15, ty = tid >> 4;
    int la_k = tid >> 5;
    int la_m = (tid & 31) * 4;
    int lw_n = tid >> 1;
    int lw_k = (tid & 1) * 4;

    for (int k0 = 0; k0 < 256; k0 += 8) {
        float4 av = *(const float4*)(Ab + (size_t)(k0 + la_k) * P_ + la_m);
        float4 wv = *(const float4*)(W + (size_t)(n0 + lw_n) * 256 + k0 + lw_k);
        __syncthreads();
        *(float4*)&As[la_k][la_m] = av;
        Ws[lw_k+0][lw_n] = wv.x; Ws[lw_k+1][lw_n] = wv.y;
        Ws[lw_k+2][lw_n] = wv.z; Ws[lw_k+3][lw_n] = wv.w;
        __syncthreads();
        #pragma unroll
        for (int kk = 0; kk < 8; kk++) {
            float a[8], bb[8];
            *(float4*)&a[0]  = *(const float4*)&As[kk][ty*8];
            *(float4*)&a[4]  = *(const float4*)&As[kk][ty*8 + 4];
            *(float4*)&bb[0] = *(const float4*)&Ws[kk][tx*8];
            *(float4*)&bb[4] = *(const float4*)&Ws[kk][tx*8 + 4];
            #pragma unroll
            for (int i = 0; i < 8; i++)
                #pragma unroll
                for (int j = 0; j < 8; j++) acc[i][j] += a[i] * bb[j];
        }
    }
    float bs[8];
    #pragma unroll
    for (int j = 0; j < 8; j++) bs[j] = bias[n0 + tx*8 + j];
    size_t mbase = (size_t)bm * 128 + ty * 8;
    #pragma unroll
    for (int i = 0; i < 8; i++) {
        float* dst = out + (mbase + i) * 256 + n0 + tx*8;
        float4 o0, o1;
        o0.x = acc[i][0]+bs[0]; o0.y = acc[i][1]+bs[1]; o0.z = acc[i][2]+bs[2]; o0.w = acc[i][3]+bs[3];
        o1.x = acc[i][4]+bs[4]; o1.y = acc[i][5]+bs[5]; o1.z = acc[i][6]+bs[6]; o1.w = acc[i][7]+bs[7];
        *(float4*)dst = o0;
        *(float4*)(dst + 4) = o1;
    }
}

// ---- kernel 5: M[bh][dv][i][w] = sum_ii attn_h[i][ii] * v[(ii,w),hd] --------
__global__ void __launch_bounds__(256) e1_kernel()
{
    __shared__ float As[64*64];
    __shared__ float Vs[64*128];   // [ii][dv*16 + w]
    int tid = threadIdx.x;
    int bh = blockIdx.x;
    int b = bh >> 3, Hh = bh & 7;
    int dt = blockIdx.y >> 2;
    int wt = blockIdx.y & 3;

    const float* Ag = g_attn[0] + (size_t)bh * 4096;
    for (int e = tid; e < 4096; e += 256) As[e] = Ag[e];

    const float* Vg = g_vlin + (size_t)b * P_ * 256 + Hh*32 + dt*8;
    for (int e = tid; e < 8192; e += 256) {
        int dv = e & 7, w = (e >> 3) & 15, ii = e >> 7;
        Vs[ii*128 + dv*16 + w] = Vg[(size_t)(ii*64 + wt*16 + w) * 256 + dv];
    }
    __syncthreads();

    int ty = tid >> 5;
    int tx = tid & 31;
    int dv = tx & 7, wg = tx >> 3;
    float acc[8][4];
    #pragma unroll
    for (int r = 0; r < 8; r++)
        #pragma unroll
        for (int q = 0; q < 4; q++) acc[r][q] = 0.f;

    #pragma unroll 2
    for (int ii = 0; ii < 64; ii++) {
        float4 v4 = *(const float4*)&Vs[ii*128 + dv*16 + wg*4];
        #pragma unroll
        for (int r = 0; r < 8; r++) {
            float a = As[(ty*8 + r)*64 + ii];
            acc[r][0] += a * v4.x; acc[r][1] += a * v4.y;
            acc[r][2] += a * v4.z; acc[r][3] += a * v4.w;
        }
    }
    float* Mb = g_M + (size_t)bh * (D_*S_*S_);
    #pragma unroll
    for (int r = 0; r < 8; r++) {
        int i = ty*8 + r;
        float4 o; o.x = acc[r][0]; o.y = acc[r][1]; o.z = acc[r][2]; o.w = acc[r][3];
        *(float4*)&Mb[(size_t)(dt*8 + dv)*4096 + i*64 + wt*16 + wg*4] = o;
    }
}

// ---- kernel 6: r[b][hd][i*64+j] = sum_w M[dv][i][w] * attn_w[w][j] ----------
__global__ void __launch_bounds__(256) e2_kernel()
{
    __shared__ float Ms[128*64];
    __shared__ float Ws[64*64];
    int tid = threadIdx.x;
    int bh = blockIdx.x;
    int b = bh >> 3, Hh = bh & 7;
    int mt = blockIdx.y;

    const float* Mg = g_M + (size_t)bh * (D_*S_*S_) + (size_t)mt * 128 * 64;
    for (int e = tid; e < 8192; e += 256) Ms[e] = Mg[e];
    const float* Wg = g_attn[1] + (size_t)bh * 4096;
    for (int e = tid; e < 4096; e += 256) Ws[e] = Wg[e];
    __syncthreads();

    int mg = tid >> 4;
    int jg = tid & 15;
    float acc[8][4];
    #pragma unroll
    for (int r = 0; r < 8; r++)
        #pragma unroll
        for (int q = 0; q < 4; q++) acc[r][q] = 0.f;

    #pragma unroll 2
    for (int w = 0; w < 64; w++) {
        float4 b4 = *(const float4*)&Ws[w*64 + jg*4];
        #pragma unroll
        for (int r = 0; r < 8; r++) {
            float a = Ms[(mg*8 + r)*64 + w];
            acc[r][0] += a * b4.x; acc[r][1] += a * b4.y;
            acc[r][2] += a * b4.z; acc[r][3] += a * b4.w;
        }
    }
    #pragma unroll
    for (int r = 0; r < 8; r++) {
        int m = mt*128 + mg*8 + r;
        int dvv = m >> 6, i = m & 63;
        float4 o; o.x = acc[r][0]; o.y = acc[r][1]; o.z = acc[r][2]; o.w = acc[r][3];
        *(float4*)(g_r + (size_t)(b*256 + Hh*32 + dvv) * P_ + i*64 + jg*4) = o;
    }
}

// ---- host launcher ----------------------------------------------------------
extern "C" void kernel_launch(void* const* d_in, const int* in_sizes, int n_in,
                              void* d_out, int out_size)
{
    const float* x = (const float*)d_in[0];
    const float* dwqh_w = (const float*)d_in[1];  const float* dwqh_b = (const float*)d_in[2];
    const float* fcqh_w = (const float*)d_in[3];  const float* fcqh_b = (const float*)d_in[4];
    const float* dwkh_w = (const float*)d_in[5];  const float* dwkh_b = (const float*)d_in[6];
    const float* fckh_w = (const float*)d_in[7];  const float* fckh_b = (const float*)d_in[8];
    const float* Bh     = (const float*)d_in[9];
    const float* dwv_w  = (const float*)d_in[10]; const float* dwv_b  = (const float*)d_in[11];
    const float* fcv_w  = (const float*)d_in[12]; const float* fcv_b  = (const float*)d_in[13];
    const float* dwqw_w = (const float*)d_in[14]; const float* dwqw_b = (const float*)d_in[15];
    const float* fcqw_w = (const float*)d_in[16]; const float* fcqw_b = (const float*)d_in[17];
    const float* dwkw_w = (const float*)d_in[18]; const float* dwkw_b = (const float*)d_in[19];
    const float* fckw_w = (const float*)d_in[20]; const float* fckw_b = (const float*)d_in[21];
    const float* Bw     = (const float*)d_in[22];
    const float* fco_w  = (const float*)d_in[23]; const float* fco_b  = (const float*)d_in[24];

    float *convv, *pool, *qk, *vlin, *r;
    cudaGetSymbolAddress((void**)&convv, g_convv);
    cudaGetSymbolAddress((void**)&pool,  g_pool);
    cudaGetSymbolAddress((void**)&qk,    g_qk);
    cudaGetSymbolAddress((void**)&vlin,  g_vlin);
    cudaGetSymbolAddress((void**)&r,     g_r);

    conv5_kernel<<<B_*C_, 256>>>(x, dwqh_w, dwqh_b, dwkh_w, dwkh_b,
                                 dwv_w, dwv_b, dwqw_w, dwqw_b, dwkw_w, dwkw_b);

    const size_t PSTRIDE = (size_t)B_*S_*C_;
    const size_t QSTRIDE = (size_t)B_*S_*HD_;
    dim3 gsm(16, 4);
    linear_rm_kernel<<<gsm, 256>>>(pool + 0*PSTRIDE, fcqh_w, fcqh_b, qk + 0*QSTRIDE, 256, 256);
    linear_rm_kernel<<<gsm, 256>>>(pool + 1*PSTRIDE, fckh_w, fckh_b, qk + 1*QSTRIDE, 256, 256);
    linear_rm_kernel<<<gsm, 256>>>(pool + 2*PSTRIDE, fcqw_w, fcqw_b, qk + 2*QSTRIDE, 256, 256);
    linear_rm_kernel<<<gsm, 256>>>(pool + 3*PSTRIDE, fckw_w, fckw_b, qk + 3*QSTRIDE, 256, 256);

    attn_kernel<<<256, 256>>>(Bh, Bw);

    linear_cm_kernel<<<dim3(512, 2), 256>>>(convv, fcv_w, fcv_b, vlin);

    e1_kernel<<<dim3(128, 16), 256>>>();
    e2_kernel<<<dim3(128, 16), 256>>>();

    linear_cm_kernel<<<dim3(512, 2), 256>>>(r, fco_w, fco_b, (float*)d_out);
}

// round 3
// speedup vs baseline: 1.0460x; 1.0460x over previous
#include <cuda_runtime.h>
#include <cuda_bf16.h>

#define B_  16
#define C_  256
#define S_  64
#define H_  8
#define D_  32
#define HD_ 256
#define P_  4096

// scratch (device globals; allocations are forbidden)
__device__ float g_convv[(size_t)B_*C_*P_];      // [b][c][p] channel-major
__device__ float g_pool[4][B_*S_*C_];            // [path][b*64+pos][c]
__device__ float g_qk[4][B_*S_*HD_];             // [path][b*64+pos][hd]
__device__ float g_attn[2][B_*H_*S_*S_];         // [axis][bh][i][j]
__device__ float g_vlin[(size_t)B_*P_*HD_];      // [b][p][hd]
__device__ float g_M[(size_t)B_*H_*D_*S_*S_];    // [bh][dv][i][w]
__device__ float g_r[(size_t)B_*HD_*P_];         // [b][hd][p]

// ---- packed f32x2 helpers ----------------------------------------------------
__device__ __forceinline__ unsigned long long pack2(float x, float y) {
    unsigned long long r;
    asm("mov.b64 %0, {%1, %2};" : "=l"(r) : "f"(x), "f"(y));
    return r;
}
__device__ __forceinline__ void fma2(unsigned long long& d, unsigned long long a,
                                     unsigned long long b) {
    asm("fma.rn.f32x2 %0, %1, %2, %0;" : "+l"(d) : "l"(a), "l"(b));
}
__device__ __forceinline__ float2 unpack2(unsigned long long v) {
    float2 f;
    asm("mov.b64 {%0, %1}, %2;" : "=f"(f.x), "=f"(f.y) : "l"(v));
    return f;
}

// ---- kernel 1: fused 5x depthwise 3x3 conv + row/col means -----------------
__global__ void __launch_bounds__(256) conv5_kernel(
    const float* __restrict__ x,
    const float* __restrict__ w_qh, const float* __restrict__ b_qh,
    const float* __restrict__ w_kh, const float* __restrict__ b_kh,
    const float* __restrict__ w_v,  const float* __restrict__ b_v,
    const float* __restrict__ w_qw, const float* __restrict__ b_qw,
    const float* __restrict__ w_kw, const float* __restrict__ b_kw)
{
    __shared__ float tile[66*66];
    __shared__ float s_row[2][64];
    __shared__ float s_colbuf[2][256];

    int b = blockIdx.x >> 8;
    int c = blockIdx.x & 255;
    int tid = threadIdx.x;

    const float* xp = x + (size_t)(b*C_ + c) * P_;
    for (int idx = tid; idx < 66*66; idx += 256) {
        int r = idx / 66 - 1, cc = idx % 66 - 1;
        float v = 0.f;
        if ((unsigned)r < 64u && (unsigned)cc < 64u) v = xp[r*64 + cc];
        tile[idx] = v;
    }
    if (tid < 64) { s_row[0][tid] = 0.f; s_row[1][tid] = 0.f; }

    float wqh[9], wkh[9], wv[9], wqw[9], wkw[9];
    #pragma unroll
    for (int k = 0; k < 9; k++) {
        wqh[k] = w_qh[c*9+k]; wkh[k] = w_kh[c*9+k]; wv[k] = w_v[c*9+k];
        wqw[k] = w_qw[c*9+k]; wkw[k] = w_kw[c*9+k];
    }
    float bqh = b_qh[c], bkh = b_kh[c], bv = b_v[c], bqw = b_qw[c], bkw = b_kw[c];
    __syncthreads();

    float acc_qw = 0.f, acc_kw = 0.f;
    int col = tid & 63;
    float* outv = g_convv + (size_t)(b*C_ + c) * P_;

    #pragma unroll 4
    for (int it = 0; it < 16; it++) {
        int p = it*256 + tid;
        int r = p >> 6;
        float n[9];
        #pragma unroll
        for (int dr = 0; dr < 3; dr++)
            #pragma unroll
            for (int dc = 0; dc < 3; dc++)
                n[dr*3+dc] = tile[(r+dr)*66 + col + dc];
        float sv = bv, sqh = bqh, skh = bkh, sqw = bqw, skw = bkw;
        #pragma unroll
        for (int k = 0; k < 9; k++) {
            sv  += wv[k]  * n[k];
            sqh += wqh[k] * n[k];
            skh += wkh[k] * n[k];
            sqw += wqw[k] * n[k];
            skw += wkw[k] * n[k];
        }
        outv[p] = sv;
        acc_qw += sqw; acc_kw += skw;
        float rq = sqh, rk = skh;   // whole warp shares row r
        #pragma unroll
        for (int o = 16; o; o >>= 1) {
            rq += __shfl_down_sync(0xffffffffu, rq, o);
            rk += __shfl_down_sync(0xffffffffu, rk, o);
        }
        if ((tid & 31) == 0) { atomicAdd(&s_row[0][r], rq); atomicAdd(&s_row[1][r], rk); }
    }
    s_colbuf[0][tid] = acc_qw;
    s_colbuf[1][tid] = acc_kw;
    __syncthreads();

    if (tid < 64) {
        float cq = s_colbuf[0][tid] + s_colbuf[0][tid+64] + s_colbuf[0][tid+128] + s_colbuf[0][tid+192];
        float ck = s_colbuf[1][tid] + s_colbuf[1][tid+64] + s_colbuf[1][tid+128] + s_colbuf[1][tid+192];
        size_t o = (size_t)(b*64 + tid) * C_ + c;
        const float inv = 1.f / 64.f;
        g_pool[0][o] = s_row[0][tid] * inv;
        g_pool[1][o] = s_row[1][tid] * inv;
        g_pool[2][o] = cq * inv;
        g_pool[3][o] = ck * inv;
    }
}

// ---- kernel 2: batched small linear (4 paths), row-major A [M,K], W[N,K] ---
__global__ void __launch_bounds__(256) linear_rm4_kernel(
    const float* __restrict__ W0, const float* __restrict__ bias0,
    const float* __restrict__ W1, const float* __restrict__ bias1,
    const float* __restrict__ W2, const float* __restrict__ bias2,
    const float* __restrict__ W3, const float* __restrict__ bias3)
{
    __shared__ float As[16][64];
    __shared__ float Ws[16][64];
    int tid = threadIdx.x;
    int path = blockIdx.z;
    const float* A    = g_pool[path];
    const float* W    = path == 0 ? W0 : path == 1 ? W1 : path == 2 ? W2 : W3;
    const float* bias = path == 0 ? bias0 : path == 1 ? bias1 : path == 2 ? bias2 : bias3;
    float* out = g_qk[path];

    int m0 = blockIdx.x * 64, n0 = blockIdx.y * 64;
    int tx = tid & 15, ty = tid >> 4;
    int l_r = tid >> 2;
    int l_k = (tid & 3) * 4;
    float acc[4][4];
    #pragma unroll
    for (int i = 0; i < 4; i++)
        #pragma unroll
        for (int j = 0; j < 4; j++) acc[i][j] = 0.f;

    for (int k0 = 0; k0 < 256; k0 += 16) {
        float4 av = *(const float4*)(A + (size_t)(m0 + l_r) * 256 + k0 + l_k);
        float4 wv = *(const float4*)(W + (size_t)(n0 + l_r) * 256 + k0 + l_k);
        __syncthreads();
        As[l_k+0][l_r] = av.x; As[l_k+1][l_r] = av.y; As[l_k+2][l_r] = av.z; As[l_k+3][l_r] = av.w;
        Ws[l_k+0][l_r] = wv.x; Ws[l_k+1][l_r] = wv.y; Ws[l_k+2][l_r] = wv.z; Ws[l_k+3][l_r] = wv.w;
        __syncthreads();
        #pragma unroll
        for (int kk = 0; kk < 16; kk++) {
            float a[4], bb[4];
            *(float4*)a  = *(const float4*)&As[kk][ty*4];
            *(float4*)bb = *(const float4*)&Ws[kk][tx*4];
            #pragma unroll
            for (int i = 0; i < 4; i++)
                #pragma unroll
                for (int j = 0; j < 4; j++) acc[i][j] += a[i] * bb[j];
        }
    }
    float bs[4];
    #pragma unroll
    for (int j = 0; j < 4; j++) bs[j] = bias[n0 + tx*4 + j];
    #pragma unroll
    for (int i = 0; i < 4; i++) {
        float4 o;
        o.x = acc[i][0] + bs[0]; o.y = acc[i][1] + bs[1];
        o.z = acc[i][2] + bs[2]; o.w = acc[i][3] + bs[3];
        *(float4*)(out + (size_t)(m0 + ty*4 + i) * 256 + n0 + tx*4) = o;
    }
}

// ---- kernel 3: attention logits + softmax -----------------------------------
__global__ void __launch_bounds__(256) attn_kernel(const float* __restrict__ Bh,
                                                   const float* __restrict__ Bw)
{
    __shared__ float Qs[64*33];
    __shared__ float Ks[64*33];
    __shared__ float L[64*65];
    int tid = threadIdx.x;
    int path = blockIdx.x >> 7;
    int bh = blockIdx.x & 127;
    int b = bh >> 3, Hh = bh & 7;

    const float* qg = g_qk[path*2]   + (size_t)(b*64) * 256 + Hh*32;
    const float* kg = g_qk[path*2+1] + (size_t)(b*64) * 256 + Hh*32;
    const float* bias = (path ? Bw : Bh) + (size_t)Hh * 4096;

    for (int e = tid; e < 2048; e += 256) {
        int i = e >> 5, d = e & 31;
        Qs[i*33+d] = qg[(size_t)i*256 + d];
        Ks[i*33+d] = kg[(size_t)i*256 + d];
    }
    __syncthreads();
    const float scale = 0.17677669529663687f;
    for (int e = tid; e < 4096; e += 256) {
        int i = e >> 6, j = e & 63;
        float s = 0.f;
        #pragma unroll
        for (int d = 0; d < 32; d++) s += Qs[i*33+d] * Ks[j*33+d];
        L[i*65+j] = s * scale + bias[i*64 + j];
    }
    __syncthreads();
    int warp = tid >> 5, lane = tid & 31;
    float* outp = g_attn[path] + (size_t)bh * 4096;
    for (int r = warp; r < 64; r += 8) {
        float v0 = L[r*65 + lane], v1 = L[r*65 + 32 + lane];
        float mx = fmaxf(v0, v1);
        #pragma unroll
        for (int o = 16; o; o >>= 1) mx = fmaxf(mx, __shfl_xor_sync(0xffffffffu, mx, o));
        float e0 = __expf(v0 - mx), e1 = __expf(v1 - mx);
        float s = e0 + e1;
        #pragma unroll
        for (int o = 16; o; o >>= 1) s += __shfl_xor_sync(0xffffffffu, s, o);
        float inv = 1.f / s;
        outp[r*64 + lane]      = e0 * inv;
        outp[r*64 + 32 + lane] = e1 * inv;
    }
}

// ---- kernel 4/7: big linear, A channel-major [b][k][p], out [b][p][n] -------
// f32x2 packed-FMA inner loop.
__global__ void __launch_bounds__(256) linear_cm_kernel(
    const float* __restrict__ Acm, const float* __restrict__ W,
    const float* __restrict__ bias, float* __restrict__ out)
{
    __shared__ float As[8][128];
    __shared__ float Ws[8][128];
    int tid = threadIdx.x;
    int bm = blockIdx.x;
    int n0 = blockIdx.y * 128;
    int b  = bm >> 5;
    int p0 = (bm & 31) * 128;
    const float* Ab = Acm + (size_t)b * C_ * P_ + p0;

    unsigned long long acc2[8][4];
    #pragma unroll
    for (int i = 0; i < 8; i++)
        #pragma unroll
        for (int j = 0; j < 4; j++) acc2[i][j] = 0ULL;

    int tx = tid & 15, ty = tid >> 4;
    int la_k = tid >> 5;
    int la_m = (tid & 31) * 4;
    int lw_n = tid >> 1;
    int lw_k = (tid & 1) * 4;

    for (int k0 = 0; k0 < 256; k0 += 8) {
        float4 av = *(const float4*)(Ab + (size_t)(k0 + la_k) * P_ + la_m);
        float4 wv = *(const float4*)(W + (size_t)(n0 + lw_n) * 256 + k0 + lw_k);
        __syncthreads();
        *(float4*)&As[la_k][la_m] = av;
        Ws[lw_k+0][lw_n] = wv.x; Ws[lw_k+1][lw_n] = wv.y;
        Ws[lw_k+2][lw_n] = wv.z; Ws[lw_k+3][lw_n] = wv.w;
        __syncthreads();
        #pragma unroll
        for (int kk = 0; kk < 8; kk++) {
            float a[8];
            *(float4*)&a[0] = *(const float4*)&As[kk][ty*8];
            *(float4*)&a[4] = *(const float4*)&As[kk][ty*8 + 4];
            const unsigned long long* wp = (const unsigned long long*)&Ws[kk][tx*8];
            unsigned long long b2[4];
            b2[0] = wp[0]; b2[1] = wp[1]; b2[2] = wp[2]; b2[3] = wp[3];
            #pragma unroll
            for (int i = 0; i < 8; i++) {
                unsigned long long a2 = pack2(a[i], a[i]);
                #pragma unroll
                for (int j = 0; j < 4; j++) fma2(acc2[i][j], a2, b2[j]);
            }
        }
    }
    float bs[8];
    #pragma unroll
    for (int j = 0; j < 8; j++) bs[j] = bias[n0 + tx*8 + j];
    size_t mbase = (size_t)bm * 128 + ty * 8;
    #pragma unroll
    for (int i = 0; i < 8; i++) {
        float* dst = out + (mbase + i) * 256 + n0 + tx*8;
        float2 p0f = unpack2(acc2[i][0]), p1f = unpack2(acc2[i][1]);
        float2 p2f = unpack2(acc2[i][2]), p3f = unpack2(acc2[i][3]);
        float4 o0, o1;
        o0.x = p0f.x+bs[0]; o0.y = p0f.y+bs[1]; o0.z = p1f.x+bs[2]; o0.w = p1f.y+bs[3];
        o1.x = p2f.x+bs[4]; o1.y = p2f.y+bs[5]; o1.z = p3f.x+bs[6]; o1.w = p3f.y+bs[7];
        *(float4*)dst = o0;
        *(float4*)(dst + 4) = o1;
    }
}

// ---- kernel 5: M[bh][dv][i][w] = sum_ii attn_h[i][ii] * v[(ii,w),hd] --------
__global__ void __launch_bounds__(256) e1_kernel()
{
    __shared__ float As[64*64];
    __shared__ float Vs[64*128];   // [ii][dv*16 + w]
    int tid = threadIdx.x;
    int bh = blockIdx.x;
    int b = bh >> 3, Hh = bh & 7;
    int dt = blockIdx.y >> 2;
    int wt = blockIdx.y & 3;

    const float* Ag = g_attn[0] + (size_t)bh * 4096;
    for (int e = tid; e < 4096; e += 256) As[e] = Ag[e];

    const float* Vg = g_vlin + (size_t)b * P_ * 256 + Hh*32 + dt*8;
    for (int e = tid; e < 8192; e += 256) {
        int dv = e & 7, w = (e >> 3) & 15, ii = e >> 7;
        Vs[ii*128 + dv*16 + w] = Vg[(size_t)(ii*64 + wt*16 + w) * 256 + dv];
    }
    __syncthreads();

    int ty = tid >> 5;
    int tx = tid & 31;
    int dv = tx & 7, wg = tx >> 3;
    unsigned long long acc2[8][2];
    #pragma unroll
    for (int r = 0; r < 8; r++) { acc2[r][0] = 0ULL; acc2[r][1] = 0ULL; }

    #pragma unroll 2
    for (int ii = 0; ii < 64; ii++) {
        const unsigned long long* vp = (const unsigned long long*)&Vs[ii*128 + dv*16 + wg*4];
        unsigned long long v0 = vp[0], v1 = vp[1];
        #pragma unroll
        for (int r = 0; r < 8; r++) {
            float a = As[(ty*8 + r)*64 + ii];
            unsigned long long a2 = pack2(a, a);
            fma2(acc2[r][0], a2, v0);
            fma2(acc2[r][1], a2, v1);
        }
    }
    float* Mb = g_M + (size_t)bh * (D_*S_*S_);
    #pragma unroll
    for (int r = 0; r < 8; r++) {
        int i = ty*8 + r;
        float2 lo = unpack2(acc2[r][0]), hi = unpack2(acc2[r][1]);
        float4 o; o.x = lo.x; o.y = lo.y; o.z = hi.x; o.w = hi.y;
        *(float4*)&Mb[(size_t)(dt*8 + dv)*4096 + i*64 + wt*16 + wg*4] = o;
    }
}

// ---- kernel 6: r[b][hd][i*64+j] = sum_w M[dv][i][w] * attn_w[w][j] ----------
__global__ void __launch_bounds__(256) e2_kernel()
{
    __shared__ float Ms[128*64];
    __shared__ float Ws[64*64];
    int tid = threadIdx.x;
    int bh = blockIdx.x;
    int b = bh >> 3, Hh = bh & 7;
    int mt = blockIdx.y;

    const float* Mg = g_M + (size_t)bh * (D_*S_*S_) + (size_t)mt * 128 * 64;
    for (int e = tid; e < 8192; e += 256) Ms[e] = Mg[e];
    const float* Wg = g_attn[1] + (size_t)bh * 4096;
    for (int e = tid; e < 4096; e += 256) Ws[e] = Wg[e];
    __syncthreads();

    int mg = tid >> 4;
    int jg = tid & 15;
    unsigned long long acc2[8][2];
    #pragma unroll
    for (int r = 0; r < 8; r++) { acc2[r][0] = 0ULL; acc2[r][1] = 0ULL; }

    #pragma unroll 2
    for (int w = 0; w < 64; w++) {
        const unsigned long long* bp = (const unsigned long long*)&Ws[w*64 + jg*4];
        unsigned long long b0 = bp[0], b1 = bp[1];
        #pragma unroll
        for (int r = 0; r < 8; r++) {
            float a = Ms[(mg*8 + r)*64 + w];
            unsigned long long a2 = pack2(a, a);
            fma2(acc2[r][0], a2, b0);
            fma2(acc2[r][1], a2, b1);
        }
    }
    #pragma unroll
    for (int r = 0; r < 8; r++) {
        int m = mt*128 + mg*8 + r;
        int dvv = m >> 6, i = m & 63;
        float2 lo = unpack2(acc2[r][0]), hi = unpack2(acc2[r][1]);
        float4 o; o.x = lo.x; o.y = lo.y; o.z = hi.x; o.w = hi.y;
        *(float4*)(g_r + (size_t)(b*256 + Hh*32 + dvv) * P_ + i*64 + jg*4) = o;
    }
}

// ---- host launcher ----------------------------------------------------------
extern "C" void kernel_launch(void* const* d_in, const int* in_sizes, int n_in,
                              void* d_out, int out_size)
{
    const float* x = (const float*)d_in[0];
    const float* dwqh_w = (const float*)d_in[1];  const float* dwqh_b = (const float*)d_in[2];
    const float* fcqh_w = (const float*)d_in[3];  const float* fcqh_b = (const float*)d_in[4];
    const float* dwkh_w = (const float*)d_in[5];  const float* dwkh_b = (const float*)d_in[6];
    const float* fckh_w = (const float*)d_in[7];  const float* fckh_b = (const float*)d_in[8];
    const float* Bh     = (const float*)d_in[9];
    const float* dwv_w  = (const float*)d_in[10]; const float* dwv_b  = (const float*)d_in[11];
    const float* fcv_w  = (const float*)d_in[12]; const float* fcv_b  = (const float*)d_in[13];
    const float* dwqw_w = (const float*)d_in[14]; const float* dwqw_b = (const float*)d_in[15];
    const float* fcqw_w = (const float*)d_in[16]; const float* fcqw_b = (const float*)d_in[17];
    const float* dwkw_w = (const float*)d_in[18]; const float* dwkw_b = (const float*)d_in[19];
    const float* fckw_w = (const float*)d_in[20]; const float* fckw_b = (const float*)d_in[21];
    const float* Bw     = (const float*)d_in[22];
    const float* fco_w  = (const float*)d_in[23]; const float* fco_b  = (const float*)d_in[24];

    float *convv, *vlin, *r;
    cudaGetSymbolAddress((void**)&convv, g_convv);
    cudaGetSymbolAddress((void**)&vlin,  g_vlin);
    cudaGetSymbolAddress((void**)&r,     g_r);

    conv5_kernel<<<B_*C_, 256>>>(x, dwqh_w, dwqh_b, dwkh_w, dwkh_b,
                                 dwv_w, dwv_b, dwqw_w, dwqw_b, dwkw_w, dwkw_b);

    linear_rm4_kernel<<<dim3(16, 4, 4), 256>>>(fcqh_w, fcqh_b, fckh_w, fckh_b,
                                               fcqw_w, fcqw_b, fckw_w, fckw_b);

    attn_kernel<<<256, 256>>>(Bh, Bw);

    linear_cm_kernel<<<dim3(512, 2), 256>>>(convv, fcv_w, fcv_b, vlin);

    e1_kernel<<<dim3(128, 16), 256>>>();
    e2_kernel<<<dim3(128, 16), 256>>>();

    linear_cm_kernel<<<dim3(512, 2), 256>>>(r, fco_w, fco_b, (float*)d_out);
}

// round 4
// speedup vs baseline: 1.2602x; 1.2048x over previous
#include <cuda_runtime.h>
#include <cuda_bf16.h>

#define B_  16
#define C_  256
#define S_  64
#define H_  8
#define D_  32
#define HD_ 256
#define P_  4096

// scratch (device globals; allocations are forbidden)
__device__ float g_convv[(size_t)B_*C_*P_];      // [b][c][p] channel-major
__device__ float g_pool[4][B_*S_*C_];            // [path][b*64+pos][c]
__device__ float g_qk[4][B_*S_*HD_];             // [path][b*64+pos][hd]
__device__ float g_attn[2][B_*H_*S_*S_];         // [axis][bh][i][j]
__device__ float g_vlin[(size_t)B_*P_*HD_];      // [b][p][hd]
__device__ float g_M[(size_t)B_*H_*D_*S_*S_];    // [bh][dv][i][w]
__device__ float g_r[(size_t)B_*HD_*P_];         // [b][hd][p]

// ---- packed f32x2 helpers ----------------------------------------------------
__device__ __forceinline__ unsigned long long pack2(float x, float y) {
    unsigned long long r;
    asm("mov.b64 %0, {%1, %2};" : "=l"(r) : "f"(x), "f"(y));
    return r;
}
__device__ __forceinline__ void fma2(unsigned long long& d, unsigned long long a,
                                     unsigned long long b) {
    asm("fma.rn.f32x2 %0, %1, %2, %0;" : "+l"(d) : "l"(a), "l"(b));
}
__device__ __forceinline__ float2 unpack2(unsigned long long v) {
    float2 f;
    asm("mov.b64 {%0, %1}, %2;" : "=f"(f.x), "=f"(f.y) : "l"(v));
    return f;
}

// ---- kernel 1: fused 5x depthwise 3x3 conv + row/col means -----------------
__global__ void __launch_bounds__(256) conv5_kernel(
    const float* __restrict__ x,
    const float* __restrict__ w_qh, const float* __restrict__ b_qh,
    const float* __restrict__ w_kh, const float* __restrict__ b_kh,
    const float* __restrict__ w_v,  const float* __restrict__ b_v,
    const float* __restrict__ w_qw, const float* __restrict__ b_qw,
    const float* __restrict__ w_kw, const float* __restrict__ b_kw)
{
    __shared__ float tile[66*66];
    __shared__ float s_row[2][64];
    __shared__ float s_colbuf[2][256];

    int b = blockIdx.x >> 8;
    int c = blockIdx.x & 255;
    int tid = threadIdx.x;

    const float* xp = x + (size_t)(b*C_ + c) * P_;
    for (int idx = tid; idx < 66*66; idx += 256) {
        int r = idx / 66 - 1, cc = idx % 66 - 1;
        float v = 0.f;
        if ((unsigned)r < 64u && (unsigned)cc < 64u) v = xp[r*64 + cc];
        tile[idx] = v;
    }
    if (tid < 64) { s_row[0][tid] = 0.f; s_row[1][tid] = 0.f; }

    float wqh[9], wkh[9], wv[9], wqw[9], wkw[9];
    #pragma unroll
    for (int k = 0; k < 9; k++) {
        wqh[k] = w_qh[c*9+k]; wkh[k] = w_kh[c*9+k]; wv[k] = w_v[c*9+k];
        wqw[k] = w_qw[c*9+k]; wkw[k] = w_kw[c*9+k];
    }
    float bqh = b_qh[c], bkh = b_kh[c], bv = b_v[c], bqw = b_qw[c], bkw = b_kw[c];
    __syncthreads();

    float acc_qw = 0.f, acc_kw = 0.f;
    int col = tid & 63;
    float* outv = g_convv + (size_t)(b*C_ + c) * P_;

    #pragma unroll 4
    for (int it = 0; it < 16; it++) {
        int p = it*256 + tid;
        int r = p >> 6;
        float n[9];
        #pragma unroll
        for (int dr = 0; dr < 3; dr++)
            #pragma unroll
            for (int dc = 0; dc < 3; dc++)
                n[dr*3+dc] = tile[(r+dr)*66 + col + dc];
        float sv = bv, sqh = bqh, skh = bkh, sqw = bqw, skw = bkw;
        #pragma unroll
        for (int k = 0; k < 9; k++) {
            sv  += wv[k]  * n[k];
            sqh += wqh[k] * n[k];
            skh += wkh[k] * n[k];
            sqw += wqw[k] * n[k];
            skw += wkw[k] * n[k];
        }
        outv[p] = sv;
        acc_qw += sqw; acc_kw += skw;
        float rq = sqh, rk = skh;   // whole warp shares row r
        #pragma unroll
        for (int o = 16; o; o >>= 1) {
            rq += __shfl_down_sync(0xffffffffu, rq, o);
            rk += __shfl_down_sync(0xffffffffu, rk, o);
        }
        if ((tid & 31) == 0) { atomicAdd(&s_row[0][r], rq); atomicAdd(&s_row[1][r], rk); }
    }
    s_colbuf[0][tid] = acc_qw;
    s_colbuf[1][tid] = acc_kw;
    __syncthreads();

    if (tid < 64) {
        float cq = s_colbuf[0][tid] + s_colbuf[0][tid+64] + s_colbuf[0][tid+128] + s_colbuf[0][tid+192];
        float ck = s_colbuf[1][tid] + s_colbuf[1][tid+64] + s_colbuf[1][tid+128] + s_colbuf[1][tid+192];
        size_t o = (size_t)(b*64 + tid) * C_ + c;
        const float inv = 1.f / 64.f;
        g_pool[0][o] = s_row[0][tid] * inv;
        g_pool[1][o] = s_row[1][tid] * inv;
        g_pool[2][o] = cq * inv;
        g_pool[3][o] = ck * inv;
    }
}

// ---- kernel 2: batched small linear (4 paths), row-major A [M,K], W[N,K] ---
__global__ void __launch_bounds__(256) linear_rm4_kernel(
    const float* __restrict__ W0, const float* __restrict__ bias0,
    const float* __restrict__ W1, const float* __restrict__ bias1,
    const float* __restrict__ W2, const float* __restrict__ bias2,
    const float* __restrict__ W3, const float* __restrict__ bias3)
{
    __shared__ float As[16][64];
    __shared__ float Ws[16][64];
    int tid = threadIdx.x;
    int path = blockIdx.z;
    const float* A    = g_pool[path];
    const float* W    = path == 0 ? W0 : path == 1 ? W1 : path == 2 ? W2 : W3;
    const float* bias = path == 0 ? bias0 : path == 1 ? bias1 : path == 2 ? bias2 : bias3;
    float* out = g_qk[path];

    int m0 = blockIdx.x * 64, n0 = blockIdx.y * 64;
    int tx = tid & 15, ty = tid >> 4;
    int l_r = tid >> 2;
    int l_k = (tid & 3) * 4;
    float acc[4][4];
    #pragma unroll
    for (int i = 0; i < 4; i++)
        #pragma unroll
        for (int j = 0; j < 4; j++) acc[i][j] = 0.f;

    for (int k0 = 0; k0 < 256; k0 += 16) {
        float4 av = *(const float4*)(A + (size_t)(m0 + l_r) * 256 + k0 + l_k);
        float4 wv = *(const float4*)(W + (size_t)(n0 + l_r) * 256 + k0 + l_k);
        __syncthreads();
        As[l_k+0][l_r] = av.x; As[l_k+1][l_r] = av.y; As[l_k+2][l_r] = av.z; As[l_k+3][l_r] = av.w;
        Ws[l_k+0][l_r] = wv.x; Ws[l_k+1][l_r] = wv.y; Ws[l_k+2][l_r] = wv.z; Ws[l_k+3][l_r] = wv.w;
        __syncthreads();
        #pragma unroll
        for (int kk = 0; kk < 16; kk++) {
            float a[4], bb[4];
            *(float4*)a  = *(const float4*)&As[kk][ty*4];
            *(float4*)bb = *(const float4*)&Ws[kk][tx*4];
            #pragma unroll
            for (int i = 0; i < 4; i++)
                #pragma unroll
                for (int j = 0; j < 4; j++) acc[i][j] += a[i] * bb[j];
        }
    }
    float bs[4];
    #pragma unroll
    for (int j = 0; j < 4; j++) bs[j] = bias[n0 + tx*4 + j];
    #pragma unroll
    for (int i = 0; i < 4; i++) {
        float4 o;
        o.x = acc[i][0] + bs[0]; o.y = acc[i][1] + bs[1];
        o.z = acc[i][2] + bs[2]; o.w = acc[i][3] + bs[3];
        *(float4*)(out + (size_t)(m0 + ty*4 + i) * 256 + n0 + tx*4) = o;
    }
}

// ---- kernel 3: attention logits + softmax -----------------------------------
__global__ void __launch_bounds__(256) attn_kernel(const float* __restrict__ Bh,
                                                   const float* __restrict__ Bw)
{
    __shared__ float Qs[64*33];
    __shared__ float Ks[64*33];
    __shared__ float L[64*65];
    int tid = threadIdx.x;
    int path = blockIdx.x >> 7;
    int bh = blockIdx.x & 127;
    int b = bh >> 3, Hh = bh & 7;

    const float* qg = g_qk[path*2]   + (size_t)(b*64) * 256 + Hh*32;
    const float* kg = g_qk[path*2+1] + (size_t)(b*64) * 256 + Hh*32;
    const float* bias = (path ? Bw : Bh) + (size_t)Hh * 4096;

    for (int e = tid; e < 2048; e += 256) {
        int i = e >> 5, d = e & 31;
        Qs[i*33+d] = qg[(size_t)i*256 + d];
        Ks[i*33+d] = kg[(size_t)i*256 + d];
    }
    __syncthreads();
    const float scale = 0.17677669529663687f;
    for (int e = tid; e < 4096; e += 256) {
        int i = e >> 6, j = e & 63;
        float s = 0.f;
        #pragma unroll
        for (int d = 0; d < 32; d++) s += Qs[i*33+d] * Ks[j*33+d];
        L[i*65+j] = s * scale + bias[i*64 + j];
    }
    __syncthreads();
    int warp = tid >> 5, lane = tid & 31;
    float* outp = g_attn[path] + (size_t)bh * 4096;
    for (int r = warp; r < 64; r += 8) {
        float v0 = L[r*65 + lane], v1 = L[r*65 + 32 + lane];
        float mx = fmaxf(v0, v1);
        #pragma unroll
        for (int o = 16; o; o >>= 1) mx = fmaxf(mx, __shfl_xor_sync(0xffffffffu, mx, o));
        float e0 = __expf(v0 - mx), e1 = __expf(v1 - mx);
        float s = e0 + e1;
        #pragma unroll
        for (int o = 16; o; o >>= 1) s += __shfl_xor_sync(0xffffffffu, s, o);
        float inv = 1.f / s;
        outp[r*64 + lane]      = e0 * inv;
        outp[r*64 + 32 + lane] = e1 * inv;
    }
}

// ---- kernel 4/7: big linear, A channel-major [b][k][p], out [b][p][n] -------
// BK=16, double-buffered smem, 4+4 fragments, f32x2 m-pair accumulators.
__global__ void __launch_bounds__(256, 2) linear_cm_kernel(
    const float* __restrict__ Acm, const float* __restrict__ W,
    const float* __restrict__ bias, float* __restrict__ out)
{
    __shared__ float As[2][16][128];
    __shared__ float Ws[2][16][128];
    int tid = threadIdx.x;
    int bm = blockIdx.x;
    int n0 = blockIdx.y * 128;
    int b  = bm >> 5;
    int p0 = (bm & 31) * 128;
    const float* Ab = Acm + (size_t)b * C_ * P_ + p0;

    int tx = tid & 15, ty = tid >> 4;
    int la_k = tid >> 4;           // 0..15
    int la_m = (tid & 15) * 8;     // 0..120
    int lw_n = tid >> 1;           // 0..127
    int lw_k = (tid & 1) * 8;      // 0 or 8

    unsigned long long acc2[4][8];
    #pragma unroll
    for (int i = 0; i < 4; i++)
        #pragma unroll
        for (int j = 0; j < 8; j++) acc2[i][j] = 0ULL;

    // prologue: load tile 0
    float4 a0 = *(const float4*)(Ab + (size_t)la_k * P_ + la_m);
    float4 a1 = *(const float4*)(Ab + (size_t)la_k * P_ + la_m + 4);
    float4 w0 = *(const float4*)(W + (size_t)(n0 + lw_n) * 256 + lw_k);
    float4 w1 = *(const float4*)(W + (size_t)(n0 + lw_n) * 256 + lw_k + 4);
    *(float4*)&As[0][la_k][la_m]     = a0;
    *(float4*)&As[0][la_k][la_m + 4] = a1;
    Ws[0][lw_k+0][lw_n] = w0.x; Ws[0][lw_k+1][lw_n] = w0.y;
    Ws[0][lw_k+2][lw_n] = w0.z; Ws[0][lw_k+3][lw_n] = w0.w;
    Ws[0][lw_k+4][lw_n] = w1.x; Ws[0][lw_k+5][lw_n] = w1.y;
    Ws[0][lw_k+6][lw_n] = w1.z; Ws[0][lw_k+7][lw_n] = w1.w;
    __syncthreads();

    #pragma unroll 1
    for (int it = 0; it < 16; ++it) {
        int cur = it & 1;
        if (it < 15) {
            const float* Ag = Ab + (size_t)((it+1)*16 + la_k) * P_ + la_m;
            a0 = *(const float4*)Ag;
            a1 = *(const float4*)(Ag + 4);
            const float* Wg = W + (size_t)(n0 + lw_n) * 256 + (it+1)*16 + lw_k;
            w0 = *(const float4*)Wg;
            w1 = *(const float4*)(Wg + 4);
        }
        #pragma unroll
        for (int kk = 0; kk < 16; ++kk) {
            ulonglong2 aA = *(const ulonglong2*)&As[cur][kk][ty*4];
            ulonglong2 aB = *(const ulonglong2*)&As[cur][kk][64 + ty*4];
            float4 wa = *(const float4*)&Ws[cur][kk][tx*4];
            float4 wb = *(const float4*)&Ws[cur][kk][64 + tx*4];
            unsigned long long b2[8];
            b2[0] = pack2(wa.x, wa.x); b2[1] = pack2(wa.y, wa.y);
            b2[2] = pack2(wa.z, wa.z); b2[3] = pack2(wa.w, wa.w);
            b2[4] = pack2(wb.x, wb.x); b2[5] = pack2(wb.y, wb.y);
            b2[6] = pack2(wb.z, wb.z); b2[7] = pack2(wb.w, wb.w);
            unsigned long long a2[4] = {aA.x, aA.y, aB.x, aB.y};
            #pragma unroll
            for (int mp = 0; mp < 4; mp++)
                #pragma unroll
                for (int j = 0; j < 8; j++) fma2(acc2[mp][j], a2[mp], b2[j]);
        }
        if (it < 15) {
            int nxt = cur ^ 1;
            *(float4*)&As[nxt][la_k][la_m]     = a0;
            *(float4*)&As[nxt][la_k][la_m + 4] = a1;
            Ws[nxt][lw_k+0][lw_n] = w0.x; Ws[nxt][lw_k+1][lw_n] = w0.y;
            Ws[nxt][lw_k+2][lw_n] = w0.z; Ws[nxt][lw_k+3][lw_n] = w0.w;
            Ws[nxt][lw_k+4][lw_n] = w1.x; Ws[nxt][lw_k+5][lw_n] = w1.y;
            Ws[nxt][lw_k+6][lw_n] = w1.z; Ws[nxt][lw_k+7][lw_n] = w1.w;
        }
        __syncthreads();
    }

    float bsA[4], bsB[4];
    #pragma unroll
    for (int j = 0; j < 4; j++) {
        bsA[j] = bias[n0 + tx*4 + j];
        bsB[j] = bias[n0 + 64 + tx*4 + j];
    }
    size_t rowbase = (size_t)bm * 128;
    #pragma unroll
    for (int mp = 0; mp < 4; mp++) {
        int m = (mp < 2) ? (ty*4 + 2*mp) : (64 + ty*4 + 2*(mp - 2));
        float lo[8], hi[8];
        #pragma unroll
        for (int j = 0; j < 8; j++) {
            float2 u = unpack2(acc2[mp][j]);
            lo[j] = u.x; hi[j] = u.y;
        }
        float* d0 = out + (rowbase + m) * 256 + n0 + tx*4;
        float4 o;
        o.x = lo[0]+bsA[0]; o.y = lo[1]+bsA[1]; o.z = lo[2]+bsA[2]; o.w = lo[3]+bsA[3];
        *(float4*)d0 = o;
        o.x = lo[4]+bsB[0]; o.y = lo[5]+bsB[1]; o.z = lo[6]+bsB[2]; o.w = lo[7]+bsB[3];
        *(float4*)(d0 + 64) = o;
        float* d1 = d0 + 256;
        o.x = hi[0]+bsA[0]; o.y = hi[1]+bsA[1]; o.z = hi[2]+bsA[2]; o.w = hi[3]+bsA[3];
        *(float4*)d1 = o;
        o.x = hi[4]+bsB[0]; o.y = hi[5]+bsB[1]; o.z = hi[6]+bsB[2]; o.w = hi[7]+bsB[3];
        *(float4*)(d1 + 64) = o;
    }
}

// ---- kernel 5: M[bh][dv][i][w] = sum_ii attn_h[i][ii] * v[(ii,w),hd] --------
__global__ void __launch_bounds__(256) e1_kernel()
{
    __shared__ float As[64*64];
    __shared__ float Vs[64*128];   // [ii][dv*16 + w]
    int tid = threadIdx.x;
    int bh = blockIdx.x;
    int b = bh >> 3, Hh = bh & 7;
    int dt = blockIdx.y >> 2;
    int wt = blockIdx.y & 3;

    const float* Ag = g_attn[0] + (size_t)bh * 4096;
    for (int e = tid; e < 4096; e += 256) As[e] = Ag[e];

    const float* Vg = g_vlin + (size_t)b * P_ * 256 + Hh*32 + dt*8;
    for (int e = tid; e < 8192; e += 256) {
        int dv = e & 7, w = (e >> 3) & 15, ii = e >> 7;
        Vs[ii*128 + dv*16 + w] = Vg[(size_t)(ii*64 + wt*16 + w) * 256 + dv];
    }
    __syncthreads();

    int ty = tid >> 5;
    int tx = tid & 31;
    int dv = tx & 7, wg = tx >> 3;
    unsigned long long acc2[8][2];
    #pragma unroll
    for (int r = 0; r < 8; r++) { acc2[r][0] = 0ULL; acc2[r][1] = 0ULL; }

    #pragma unroll 2
    for (int ii = 0; ii < 64; ii++) {
        ulonglong2 vv = *(const ulonglong2*)&Vs[ii*128 + dv*16 + wg*4];
        #pragma unroll
        for (int r = 0; r < 8; r++) {
            float a = As[(ty*8 + r)*64 + ii];
            unsigned long long a2 = pack2(a, a);
            fma2(acc2[r][0], a2, vv.x);
            fma2(acc2[r][1], a2, vv.y);
        }
    }
    float* Mb = g_M + (size_t)bh * (D_*S_*S_);
    #pragma unroll
    for (int r = 0; r < 8; r++) {
        int i = ty*8 + r;
        float2 lo = unpack2(acc2[r][0]), hi = unpack2(acc2[r][1]);
        float4 o; o.x = lo.x; o.y = lo.y; o.z = hi.x; o.w = hi.y;
        *(float4*)&Mb[(size_t)(dt*8 + dv)*4096 + i*64 + wt*16 + wg*4] = o;
    }
}

// ---- kernel 6: r[b][hd][i*64+j] = sum_w M[dv][i][w] * attn_w[w][j] ----------
__global__ void __launch_bounds__(256) e2_kernel()
{
    __shared__ float Ms[128*64];
    __shared__ float Ws[64*64];
    int tid = threadIdx.x;
    int bh = blockIdx.x;
    int b = bh >> 3, Hh = bh & 7;
    int mt = blockIdx.y;

    const float* Mg = g_M + (size_t)bh * (D_*S_*S_) + (size_t)mt * 128 * 64;
    for (int e = tid; e < 8192; e += 256) Ms[e] = Mg[e];
    const float* Wg = g_attn[1] + (size_t)bh * 4096;
    for (int e = tid; e < 4096; e += 256) Ws[e] = Wg[e];
    __syncthreads();

    int mg = tid >> 4;
    int jg = tid & 15;
    unsigned long long acc2[8][2];
    #pragma unroll
    for (int r = 0; r < 8; r++) { acc2[r][0] = 0ULL; acc2[r][1] = 0ULL; }

    #pragma unroll 2
    for (int w = 0; w < 64; w++) {
        ulonglong2 bb = *(const ulonglong2*)&Ws[w*64 + jg*4];
        #pragma unroll
        for (int r = 0; r < 8; r++) {
            float a = Ms[(mg*8 + r)*64 + w];
            unsigned long long a2 = pack2(a, a);
            fma2(acc2[r][0], a2, bb.x);
            fma2(acc2[r][1], a2, bb.y);
        }
    }
    #pragma unroll
    for (int r = 0; r < 8; r++) {
        int m = mt*128 + mg*8 + r;
        int dvv = m >> 6, i = m & 63;
        float2 lo = unpack2(acc2[r][0]), hi = unpack2(acc2[r][1]);
        float4 o; o.x = lo.x; o.y = lo.y; o.z = hi.x; o.w = hi.y;
        *(float4*)(g_r + (size_t)(b*256 + Hh*32 + dvv) * P_ + i*64 + jg*4) = o;
    }
}

// ---- host launcher ----------------------------------------------------------
extern "C" void kernel_launch(void* const* d_in, const int* in_sizes, int n_in,
                              void* d_out, int out_size)
{
    const float* x = (const float*)d_in[0];
    const float* dwqh_w = (const float*)d_in[1];  const float* dwqh_b = (const float*)d_in[2];
    const float* fcqh_w = (const float*)d_in[3];  const float* fcqh_b = (const float*)d_in[4];
    const float* dwkh_w = (const float*)d_in[5];  const float* dwkh_b = (const float*)d_in[6];
    const float* fckh_w = (const float*)d_in[7];  const float* fckh_b = (const float*)d_in[8];
    const float* Bh     = (const float*)d_in[9];
    const float* dwv_w  = (const float*)d_in[10]; const float* dwv_b  = (const float*)d_in[11];
    const float* fcv_w  = (const float*)d_in[12]; const float* fcv_b  = (const float*)d_in[13];
    const float* dwqw_w = (const float*)d_in[14]; const float* dwqw_b = (const float*)d_in[15];
    const float* fcqw_w = (const float*)d_in[16]; const float* fcqw_b = (const float*)d_in[17];
    const float* dwkw_w = (const float*)d_in[18]; const float* dwkw_b = (const float*)d_in[19];
    const float* fckw_w = (const float*)d_in[20]; const float* fckw_b = (const float*)d_in[21];
    const float* Bw     = (const float*)d_in[22];
    const float* fco_w  = (const float*)d_in[23]; const float* fco_b  = (const float*)d_in[24];

    float *convv, *vlin, *r;
    cudaGetSymbolAddress((void**)&convv, g_convv);
    cudaGetSymbolAddress((void**)&vlin,  g_vlin);
    cudaGetSymbolAddress((void**)&r,     g_r);

    conv5_kernel<<<B_*C_, 256>>>(x, dwqh_w, dwqh_b, dwkh_w, dwkh_b,
                                 dwv_w, dwv_b, dwqw_w, dwqw_b, dwkw_w, dwkw_b);

    linear_rm4_kernel<<<dim3(16, 4, 4), 256>>>(fcqh_w, fcqh_b, fckh_w, fckh_b,
                                               fcqw_w, fcqw_b, fckw_w, fckw_b);

    attn_kernel<<<256, 256>>>(Bh, Bw);

    linear_cm_kernel<<<dim3(512, 2), 256>>>(convv, fcv_w, fcv_b, vlin);

    e1_kernel<<<dim3(128, 16), 256>>>();
    e2_kernel<<<dim3(128, 16), 256>>>();

    linear_cm_kernel<<<dim3(512, 2), 256>>>(r, fco_w, fco_b, (float*)d_out);
}

// round 6
// speedup vs baseline: 1.4360x; 1.1394x over previous
#include <cuda_runtime.h>
#include <cuda_bf16.h>
#include <cstdint>

#define B_  16
#define C_  256
#define S_  64
#define H_  8
#define D_  32
#define HD_ 256
#define P_  4096

// scratch (device globals; allocations are forbidden)
__device__ float g_convv[(size_t)B_*C_*P_];      // [b][c][p] channel-major
__device__ float g_pool[4][B_*S_*C_];            // [path][b*64+pos][c]
__device__ float g_qk[4][B_*S_*HD_];             // [path][b*64+pos][hd]
__device__ float g_attn[2][B_*H_*S_*S_];         // [axis][bh][i][j]
__device__ float g_vlin[(size_t)B_*P_*HD_];      // [b][p][hd]
__device__ float g_M[(size_t)B_*H_*D_*S_*S_];    // [bh][dv][i][w]
__device__ float g_r[(size_t)B_*HD_*P_];         // [b][hd][p]
__device__ __nv_bfloat16 g_a_hi[(size_t)B_*P_*HD_];  // token-major [b][p][k]
__device__ __nv_bfloat16 g_a_lo[(size_t)B_*P_*HD_];
__device__ __nv_bfloat16 g_w2_hi[2][C_*HD_];
__device__ __nv_bfloat16 g_w2_lo[2][C_*HD_];

// ---- packed f32x2 helpers ----------------------------------------------------
__device__ __forceinline__ unsigned long long pack2(float x, float y) {
    unsigned long long r;
    asm("mov.b64 %0, {%1, %2};" : "=l"(r) : "f"(x), "f"(y));
    return r;
}
__device__ __forceinline__ void fma2(unsigned long long& d, unsigned long long a,
                                     unsigned long long b) {
    asm("fma.rn.f32x2 %0, %1, %2, %0;" : "+l"(d) : "l"(a), "l"(b));
}
__device__ __forceinline__ float2 unpack2(unsigned long long v) {
    float2 f;
    asm("mov.b64 {%0, %1}, %2;" : "=f"(f.x), "=f"(f.y) : "l"(v));
    return f;
}

// ---- warp-mma helpers ----------------------------------------------------------
__device__ __forceinline__ uint32_t smem_u32(const void* p) {
    uint32_t a;
    asm("{ .reg .u64 t; cvta.to.shared.u64 t, %1; cvt.u32.u64 %0, t; }" : "=r"(a) : "l"(p));
    return a;
}
__device__ __forceinline__ void ldm_x4(uint32_t addr, uint32_t* r) {
    asm volatile("ldmatrix.sync.aligned.m8n8.x4.shared.b16 {%0,%1,%2,%3}, [%4];"
                 : "=r"(r[0]), "=r"(r[1]), "=r"(r[2]), "=r"(r[3]) : "r"(addr));
}
__device__ __forceinline__ void ldm_x2(uint32_t addr, uint32_t* r) {
    asm volatile("ldmatrix.sync.aligned.m8n8.x2.shared.b16 {%0,%1}, [%2];"
                 : "=r"(r[0]), "=r"(r[1]) : "r"(addr));
}
__device__ __forceinline__ void mma_bf16(float* c, const uint32_t* a, const uint32_t* b) {
    asm volatile(
        "mma.sync.aligned.m16n8k16.row.col.f32.bf16.bf16.f32 "
        "{%0,%1,%2,%3}, {%4,%5,%6,%7}, {%8,%9}, {%0,%1,%2,%3};"
        : "+f"(c[0]), "+f"(c[1]), "+f"(c[2]), "+f"(c[3])
        : "r"(a[0]), "r"(a[1]), "r"(a[2]), "r"(a[3]), "r"(b[0]), "r"(b[1]));
}

// ---- kernel 1: fused 5x depthwise 3x3 conv + row/col means -----------------
__global__ void __launch_bounds__(256) conv5_kernel(
    const float* __restrict__ x,
    const float* __restrict__ w_qh, const float* __restrict__ b_qh,
    const float* __restrict__ w_kh, const float* __restrict__ b_kh,
    const float* __restrict__ w_v,  const float* __restrict__ b_v,
    const float* __restrict__ w_qw, const float* __restrict__ b_qw,
    const float* __restrict__ w_kw, const float* __restrict__ b_kw)
{
    __shared__ float tile[66*66];
    __shared__ float s_row[2][64];
    __shared__ float s_colbuf[2][256];

    int b = blockIdx.x >> 8;
    int c = blockIdx.x & 255;
    int tid = threadIdx.x;

    const float* xp = x + (size_t)(b*C_ + c) * P_;
    for (int idx = tid; idx < 66*66; idx += 256) {
        int r = idx / 66 - 1, cc = idx % 66 - 1;
        float v = 0.f;
        if ((unsigned)r < 64u && (unsigned)cc < 64u) v = xp[r*64 + cc];
        tile[idx] = v;
    }
    if (tid < 64) { s_row[0][tid] = 0.f; s_row[1][tid] = 0.f; }

    float wqh[9], wkh[9], wv[9], wqw[9], wkw[9];
    #pragma unroll
    for (int k = 0; k < 9; k++) {
        wqh[k] = w_qh[c*9+k]; wkh[k] = w_kh[c*9+k]; wv[k] = w_v[c*9+k];
        wqw[k] = w_qw[c*9+k]; wkw[k] = w_kw[c*9+k];
    }
    float bqh = b_qh[c], bkh = b_kh[c], bv = b_v[c], bqw = b_qw[c], bkw = b_kw[c];
    __syncthreads();

    float acc_qw = 0.f, acc_kw = 0.f;
    int col = tid & 63;
    float* outv = g_convv + (size_t)(b*C_ + c) * P_;

    #pragma unroll 4
    for (int it = 0; it < 16; it++) {
        int p = it*256 + tid;
        int r = p >> 6;
        float n[9];
        #pragma unroll
        for (int dr = 0; dr < 3; dr++)
            #pragma unroll
            for (int dc = 0; dc < 3; dc++)
                n[dr*3+dc] = tile[(r+dr)*66 + col + dc];
        float sv = bv, sqh = bqh, skh = bkh, sqw = bqw, skw = bkw;
        #pragma unroll
        for (int k = 0; k < 9; k++) {
            sv  += wv[k]  * n[k];
            sqh += wqh[k] * n[k];
            skh += wkh[k] * n[k];
            sqw += wqw[k] * n[k];
            skw += wkw[k] * n[k];
        }
        outv[p] = sv;
        acc_qw += sqw; acc_kw += skw;
        float rq = sqh, rk = skh;   // whole warp shares row r
        #pragma unroll
        for (int o = 16; o; o >>= 1) {
            rq += __shfl_down_sync(0xffffffffu, rq, o);
            rk += __shfl_down_sync(0xffffffffu, rk, o);
        }
        if ((tid & 31) == 0) { atomicAdd(&s_row[0][r], rq); atomicAdd(&s_row[1][r], rk); }
    }
    s_colbuf[0][tid] = acc_qw;
    s_colbuf[1][tid] = acc_kw;
    __syncthreads();

    if (tid < 64) {
        float cq = s_colbuf[0][tid] + s_colbuf[0][tid+64] + s_colbuf[0][tid+128] + s_colbuf[0][tid+192];
        float ck = s_colbuf[1][tid] + s_colbuf[1][tid+64] + s_colbuf[1][tid+128] + s_colbuf[1][tid+192];
        size_t o = (size_t)(b*64 + tid) * C_ + c;
        const float inv = 1.f / 64.f;
        g_pool[0][o] = s_row[0][tid] * inv;
        g_pool[1][o] = s_row[1][tid] * inv;
        g_pool[2][o] = cq * inv;
        g_pool[3][o] = ck * inv;
    }
}

// ---- kernel 2: batched small linear (4 paths), row-major A [M,K], W[N,K] ---
__global__ void __launch_bounds__(256) linear_rm4_kernel(
    const float* __restrict__ W0, const float* __restrict__ bias0,
    const float* __restrict__ W1, const float* __restrict__ bias1,
    const float* __restrict__ W2, const float* __restrict__ bias2,
    const float* __restrict__ W3, const float* __restrict__ bias3)
{
    __shared__ float As[16][64];
    __shared__ float Ws[16][64];
    int tid = threadIdx.x;
    int path = blockIdx.z;
    const float* A    = g_pool[path];
    const float* W    = path == 0 ? W0 : path == 1 ? W1 : path == 2 ? W2 : W3;
    const float* bias = path == 0 ? bias0 : path == 1 ? bias1 : path == 2 ? bias2 : bias3;
    float* out = g_qk[path];

    int m0 = blockIdx.x * 64, n0 = blockIdx.y * 64;
    int tx = tid & 15, ty = tid >> 4;
    int l_r = tid >> 2;
    int l_k = (tid & 3) * 4;
    float acc[4][4];
    #pragma unroll
    for (int i = 0; i < 4; i++)
        #pragma unroll
        for (int j = 0; j < 4; j++) acc[i][j] = 0.f;

    for (int k0 = 0; k0 < 256; k0 += 16) {
        float4 av = *(const float4*)(A + (size_t)(m0 + l_r) * 256 + k0 + l_k);
        float4 wv = *(const float4*)(W + (size_t)(n0 + l_r) * 256 + k0 + l_k);
        __syncthreads();
        As[l_k+0][l_r] = av.x; As[l_k+1][l_r] = av.y; As[l_k+2][l_r] = av.z; As[l_k+3][l_r] = av.w;
        Ws[l_k+0][l_r] = wv.x; Ws[l_k+1][l_r] = wv.y; Ws[l_k+2][l_r] = wv.z; Ws[l_k+3][l_r] = wv.w;
        __syncthreads();
        #pragma unroll
        for (int kk = 0; kk < 16; kk++) {
            float a[4], bb[4];
            *(float4*)a  = *(const float4*)&As[kk][ty*4];
            *(float4*)bb = *(const float4*)&Ws[kk][tx*4];
            #pragma unroll
            for (int i = 0; i < 4; i++)
                #pragma unroll
                for (int j = 0; j < 4; j++) acc[i][j] += a[i] * bb[j];
        }
    }
    float bs[4];
    #pragma unroll
    for (int j = 0; j < 4; j++) bs[j] = bias[n0 + tx*4 + j];
    #pragma unroll
    for (int i = 0; i < 4; i++) {
        float4 o;
        o.x = acc[i][0] + bs[0]; o.y = acc[i][1] + bs[1];
        o.z = acc[i][2] + bs[2]; o.w = acc[i][3] + bs[3];
        *(float4*)(out + (size_t)(m0 + ty*4 + i) * 256 + n0 + tx*4) = o;
    }
}

// ---- kernel 3: attention logits + softmax -----------------------------------
__global__ void __launch_bounds__(256) attn_kernel(const float* __restrict__ Bh,
                                                   const float* __restrict__ Bw)
{
    __shared__ float Qs[64*33];
    __shared__ float Ks[64*33];
    __shared__ float L[64*65];
    int tid = threadIdx.x;
    int path = blockIdx.x >> 7;
    int bh = blockIdx.x & 127;
    int b = bh >> 3, Hh = bh & 7;

    const float* qg = g_qk[path*2]   + (size_t)(b*64) * 256 + Hh*32;
    const float* kg = g_qk[path*2+1] + (size_t)(b*64) * 256 + Hh*32;
    const float* bias = (path ? Bw : Bh) + (size_t)Hh * 4096;

    for (int e = tid; e < 2048; e += 256) {
        int i = e >> 5, d = e & 31;
        Qs[i*33+d] = qg[(size_t)i*256 + d];
        Ks[i*33+d] = kg[(size_t)i*256 + d];
    }
    __syncthreads();
    const float scale = 0.17677669529663687f;
    for (int e = tid; e < 4096; e += 256) {
        int i = e >> 6, j = e & 63;
        float s = 0.f;
        #pragma unroll
        for (int d = 0; d < 32; d++) s += Qs[i*33+d] * Ks[j*33+d];
        L[i*65+j] = s * scale + bias[i*64 + j];
    }
    __syncthreads();
    int warp = tid >> 5, lane = tid & 31;
    float* outp = g_attn[path] + (size_t)bh * 4096;
    for (int r = warp; r < 64; r += 8) {
        float v0 = L[r*65 + lane], v1 = L[r*65 + 32 + lane];
        float mx = fmaxf(v0, v1);
        #pragma unroll
        for (int o = 16; o; o >>= 1) mx = fmaxf(mx, __shfl_xor_sync(0xffffffffu, mx, o));
        float e0 = __expf(v0 - mx), e1 = __expf(v1 - mx);
        float s = e0 + e1;
        #pragma unroll
        for (int o = 16; o; o >>= 1) s += __shfl_xor_sync(0xffffffffu, s, o);
        float inv = 1.f / s;
        outp[r*64 + lane]      = e0 * inv;
        outp[r*64 + 32 + lane] = e1 * inv;
    }
}

// ---- weight convert: fp32 [n][k] -> bf16 hi/lo --------------------------------
__global__ void __launch_bounds__(256) wconv_kernel(const float* __restrict__ Wv,
                                                    const float* __restrict__ Wo)
{
    int which = blockIdx.y;
    const float* src = which ? Wo : Wv;
    __nv_bfloat16* hi = g_w2_hi[which];
    __nv_bfloat16* lo = g_w2_lo[which];
    int idx = (blockIdx.x * 256 + threadIdx.x) * 4;
    float4 v = *(const float4*)(src + idx);
    __nv_bfloat16 h0 = __float2bfloat16(v.x), h1 = __float2bfloat16(v.y);
    __nv_bfloat16 h2 = __float2bfloat16(v.z), h3 = __float2bfloat16(v.w);
    __nv_bfloat16 l0 = __float2bfloat16(v.x - __bfloat162float(h0));
    __nv_bfloat16 l1 = __float2bfloat16(v.y - __bfloat162float(h1));
    __nv_bfloat16 l2 = __float2bfloat16(v.z - __bfloat162float(h2));
    __nv_bfloat16 l3 = __float2bfloat16(v.w - __bfloat162float(h3));
    uint32_t uh0 = ((uint32_t)__bfloat16_as_ushort(h1) << 16) | __bfloat16_as_ushort(h0);
    uint32_t uh1 = ((uint32_t)__bfloat16_as_ushort(h3) << 16) | __bfloat16_as_ushort(h2);
    uint32_t ul0 = ((uint32_t)__bfloat16_as_ushort(l1) << 16) | __bfloat16_as_ushort(l0);
    uint32_t ul1 = ((uint32_t)__bfloat16_as_ushort(l3) << 16) | __bfloat16_as_ushort(l2);
    *(uint2*)(hi + idx) = make_uint2(uh0, uh1);
    *(uint2*)(lo + idx) = make_uint2(ul0, ul1);
}

// ---- activation transpose+convert: fp32 [b][k][p] -> bf16 [b][p][k] hi/lo ----
__global__ void __launch_bounds__(256) atrans_kernel(const float* __restrict__ src)
{
    __shared__ float ts[64][65];
    int tid = threadIdx.x;
    int b = blockIdx.z, k0 = blockIdx.y * 64, p0 = blockIdx.x * 64;
    const float* s = src + ((size_t)(b*256 + k0)) * P_ + p0;
    int pq = (tid & 15) * 4, kr = tid >> 4;
    #pragma unroll
    for (int i = 0; i < 4; i++) {
        int k = kr + 16*i;
        float4 v = *(const float4*)(s + (size_t)k * P_ + pq);
        ts[k][pq+0] = v.x; ts[k][pq+1] = v.y; ts[k][pq+2] = v.z; ts[k][pq+3] = v.w;
    }
    __syncthreads();
    int kq = (tid & 15) * 4, pr = tid >> 4;
    #pragma unroll
    for (int i = 0; i < 4; i++) {
        int p = pr + 16*i;
        float a0 = ts[kq+0][p], a1 = ts[kq+1][p], a2 = ts[kq+2][p], a3 = ts[kq+3][p];
        __nv_bfloat16 h0 = __float2bfloat16(a0), h1 = __float2bfloat16(a1);
        __nv_bfloat16 h2 = __float2bfloat16(a2), h3 = __float2bfloat16(a3);
        __nv_bfloat16 l0 = __float2bfloat16(a0 - __bfloat162float(h0));
        __nv_bfloat16 l1 = __float2bfloat16(a1 - __bfloat162float(h1));
        __nv_bfloat16 l2 = __float2bfloat16(a2 - __bfloat162float(h2));
        __nv_bfloat16 l3 = __float2bfloat16(a3 - __bfloat162float(h3));
        size_t o = ((size_t)(b*P_ + p0 + p)) * 256 + k0 + kq;
        uint32_t uh0 = ((uint32_t)__bfloat16_as_ushort(h1) << 16) | __bfloat16_as_ushort(h0);
        uint32_t uh1 = ((uint32_t)__bfloat16_as_ushort(h3) << 16) | __bfloat16_as_ushort(h2);
        uint32_t ul0 = ((uint32_t)__bfloat16_as_ushort(l1) << 16) | __bfloat16_as_ushort(l0);
        uint32_t ul1 = ((uint32_t)__bfloat16_as_ushort(l3) << 16) | __bfloat16_as_ushort(l2);
        *(uint2*)(g_a_hi + o) = make_uint2(uh0, uh1);
        *(uint2*)(g_a_lo + o) = make_uint2(ul0, ul1);
    }
}

// ---- hmma_linear: mma.sync bf16 split GEMM ----------------------------------
// out[m][n] = sum_k A[m][k]*W[n][k] + bias[n], A/W as bf16 hi+lo pairs.
// CTA tile 128x128, K-chunk 32, 8 warps, warp tile 64x32.
__global__ void __launch_bounds__(256) hmma_linear_kernel(
    const __nv_bfloat16* __restrict__ aH, const __nv_bfloat16* __restrict__ aL,
    const __nv_bfloat16* __restrict__ wH, const __nv_bfloat16* __restrict__ wL,
    const float* __restrict__ bias, float* __restrict__ out)
{
    __shared__ __align__(16) __nv_bfloat16 sAH[128][40];
    __shared__ __align__(16) __nv_bfloat16 sAL[128][40];
    __shared__ __align__(16) __nv_bfloat16 sWH[128][40];
    __shared__ __align__(16) __nv_bfloat16 sWL[128][40];

    int tid = threadIdx.x, lane = tid & 31, wid = tid >> 5;
    int warp_m = wid >> 2, warp_n = wid & 3;
    int bm = blockIdx.x, n0 = blockIdx.y * 128;

    float acc[4][4][4];
    #pragma unroll
    for (int i = 0; i < 4; i++)
        #pragma unroll
        for (int j = 0; j < 4; j++)
            #pragma unroll
            for (int q = 0; q < 4; q++) acc[i][j][q] = 0.f;

    uint32_t bAH = smem_u32(sAH), bAL = smem_u32(sAL);
    uint32_t bWH = smem_u32(sWH), bWL = smem_u32(sWL);
    int arow = warp_m*64 + ((lane >> 3) & 1)*8 + (lane & 7);
    int acol = (lane >> 4)*8;
    int brow = warp_n*32 + (lane & 7);
    int bcol = ((lane >> 3) & 1)*8;

    const size_t abase = ((size_t)bm * 128) * 256;
    const size_t wbase = ((size_t)n0) * 256;

    #pragma unroll 1
    for (int kc = 0; kc < 8; ++kc) {
        int k0 = kc * 32;
        #pragma unroll
        for (int q = 0; q < 2; ++q) {
            int u = q*256 + tid;
            int r = u >> 2, c = (u & 3) * 8;
            size_t ga = abase + (size_t)r*256 + k0 + c;
            size_t gw = wbase + (size_t)r*256 + k0 + c;
            *(uint4*)&sAH[r][c] = *(const uint4*)(aH + ga);
            *(uint4*)&sAL[r][c] = *(const uint4*)(aL + ga);
            *(uint4*)&sWH[r][c] = *(const uint4*)(wH + gw);
            *(uint4*)&sWL[r][c] = *(const uint4*)(wL + gw);
        }
        __syncthreads();
        #pragma unroll
        for (int s = 0; s < 2; ++s) {
            uint32_t ah[4][4], al[4][4];
            int colA = s*16 + acol;
            #pragma unroll
            for (int mt = 0; mt < 4; ++mt) {
                uint32_t off = (uint32_t)(((arow + mt*16)*40 + colA) * 2);
                ldm_x4(bAH + off, ah[mt]);
                ldm_x4(bAL + off, al[mt]);
            }
            int colB = s*16 + bcol;
            #pragma unroll
            for (int nt = 0; nt < 4; ++nt) {
                uint32_t off = (uint32_t)(((brow + nt*8)*40 + colB) * 2);
                uint32_t wh2[2], wl2[2];
                ldm_x2(bWH + off, wh2);
                ldm_x2(bWL + off, wl2);
                #pragma unroll
                for (int mt = 0; mt < 4; ++mt) {
                    mma_bf16(acc[mt][nt], ah[mt], wh2);
                    mma_bf16(acc[mt][nt], ah[mt], wl2);
                    mma_bf16(acc[mt][nt], al[mt], wh2);
                }
            }
        }
        __syncthreads();
    }

    int g = lane >> 2, t = lane & 3;
    #pragma unroll
    for (int nt = 0; nt < 4; ++nt) {
        int col = n0 + warp_n*32 + nt*8 + 2*t;
        float2 bv = *(const float2*)(bias + col);
        #pragma unroll
        for (int mt = 0; mt < 4; ++mt) {
            size_t row = (size_t)bm*128 + warp_m*64 + mt*16 + g;
            float2 o0, o1;
            o0.x = acc[mt][nt][0] + bv.x; o0.y = acc[mt][nt][1] + bv.y;
            o1.x = acc[mt][nt][2] + bv.x; o1.y = acc[mt][nt][3] + bv.y;
            *(float2*)(out + row*256 + col) = o0;
            *(float2*)(out + (row + 8)*256 + col) = o1;
        }
    }
}

// ---- kernel 5: M[bh][dv][i][w] = sum_ii attn_h[i][ii] * v[(ii,w),hd] --------
__global__ void __launch_bounds__(256) e1_kernel()
{
    __shared__ float As[64*64];
    __shared__ float Vs[64*128];   // [ii][dv*16 + w]
    int tid = threadIdx.x;
    int bh = blockIdx.x;
    int b = bh >> 3, Hh = bh & 7;
    int dt = blockIdx.y >> 2;
    int wt = blockIdx.y & 3;

    const float* Ag = g_attn[0] + (size_t)bh * 4096;
    for (int e = tid; e < 4096; e += 256) As[e] = Ag[e];

    const float* Vg = g_vlin + (size_t)b * P_ * 256 + Hh*32 + dt*8;
    for (int e = tid; e < 8192; e += 256) {
        int dv = e & 7, w = (e >> 3) & 15, ii = e >> 7;
        Vs[ii*128 + dv*16 + w] = Vg[(size_t)(ii*64 + wt*16 + w) * 256 + dv];
    }
    __syncthreads();

    int ty = tid >> 5;
    int tx = tid & 31;
    int dv = tx & 7, wg = tx >> 3;
    unsigned long long acc2[8][2];
    #pragma unroll
    for (int r = 0; r < 8; r++) { acc2[r][0] = 0ULL; acc2[r][1] = 0ULL; }

    #pragma unroll 2
    for (int ii = 0; ii < 64; ii++) {
        ulonglong2 vv = *(const ulonglong2*)&Vs[ii*128 + dv*16 + wg*4];
        #pragma unroll
        for (int r = 0; r < 8; r++) {
            float a = As[(ty*8 + r)*64 + ii];
            unsigned long long a2 = pack2(a, a);
            fma2(acc2[r][0], a2, vv.x);
            fma2(acc2[r][1], a2, vv.y);
        }
    }
    float* Mb = g_M + (size_t)bh * (D_*S_*S_);
    #pragma unroll
    for (int r = 0; r < 8; r++) {
        int i = ty*8 + r;
        float2 lo = unpack2(acc2[r][0]), hi = unpack2(acc2[r][1]);
        float4 o; o.x = lo.x; o.y = lo.y; o.z = hi.x; o.w = hi.y;
        *(float4*)&Mb[(size_t)(dt*8 + dv)*4096 + i*64 + wt*16 + wg*4] = o;
    }
}

// ---- kernel 6: r[b][hd][i*64+j] = sum_w M[dv][i][w] * attn_w[w][j] ----------
__global__ void __launch_bounds__(256) e2_kernel()
{
    __shared__ float Ms[128*64];
    __shared__ float Ws[64*64];
    int tid = threadIdx.x;
    int bh = blockIdx.x;
    int b = bh >> 3, Hh = bh & 7;
    int mt = blockIdx.y;

    const float* Mg = g_M + (size_t)bh * (D_*S_*S_) + (size_t)mt * 128 * 64;
    for (int e = tid; e < 8192; e += 256) Ms[e] = Mg[e];
    const float* Wg = g_attn[1] + (size_t)bh * 4096;
    for (int e = tid; e < 4096; e += 256) Ws[e] = Wg[e];
    __syncthreads();

    int mg = tid >> 4;
    int jg = tid & 15;
    unsigned long long acc2[8][2];
    #pragma unroll
    for (int r = 0; r < 8; r++) { acc2[r][0] = 0ULL; acc2[r][1] = 0ULL; }

    #pragma unroll 2
    for (int w = 0; w < 64; w++) {
        ulonglong2 bb = *(const ulonglong2*)&Ws[w*64 + jg*4];
        #pragma unroll
        for (int r = 0; r < 8; r++) {
            float a = Ms[(mg*8 + r)*64 + w];
            unsigned long long a2 = pack2(a, a);
            fma2(acc2[r][0], a2, bb.x);
            fma2(acc2[r][1], a2, bb.y);
        }
    }
    #pragma unroll
    for (int r = 0; r < 8; r++) {
        int m = mt*128 + mg*8 + r;
        int dvv = m >> 6, i = m & 63;
        float2 lo = unpack2(acc2[r][0]), hi = unpack2(acc2[r][1]);
        float4 o; o.x = lo.x; o.y = lo.y; o.z = hi.x; o.w = hi.y;
        *(float4*)(g_r + (size_t)(b*256 + Hh*32 + dvv) * P_ + i*64 + jg*4) = o;
    }
}

// ---- host launcher ----------------------------------------------------------
extern "C" void kernel_launch(void* const* d_in, const int* in_sizes, int n_in,
                              void* d_out, int out_size)
{
    const float* x = (const float*)d_in[0];
    const float* dwqh_w = (const float*)d_in[1];  const float* dwqh_b = (const float*)d_in[2];
    const float* fcqh_w = (const float*)d_in[3];  const float* fcqh_b = (const float*)d_in[4];
    const float* dwkh_w = (const float*)d_in[5];  const float* dwkh_b = (const float*)d_in[6];
    const float* fckh_w = (const float*)d_in[7];  const float* fckh_b = (const float*)d_in[8];
    const float* Bh     = (const float*)d_in[9];
    const float* dwv_w  = (const float*)d_in[10]; const float* dwv_b  = (const float*)d_in[11];
    const float* fcv_w  = (const float*)d_in[12]; const float* fcv_b  = (const float*)d_in[13];
    const float* dwqw_w = (const float*)d_in[14]; const float* dwqw_b = (const float*)d_in[15];
    const float* fcqw_w = (const float*)d_in[16]; const float* fcqw_b = (const float*)d_in[17];
    const float* dwkw_w = (const float*)d_in[18]; const float* dwkw_b = (const float*)d_in[19];
    const float* fckw_w = (const float*)d_in[20]; const float* fckw_b = (const float*)d_in[21];
    const float* Bw     = (const float*)d_in[22];
    const float* fco_w  = (const float*)d_in[23]; const float* fco_b  = (const float*)d_in[24];

    float *convv, *r, *vlin;
    __nv_bfloat16 *ahi, *alo, *whi, *wlo;
    cudaGetSymbolAddress((void**)&convv, g_convv);
    cudaGetSymbolAddress((void**)&r,     g_r);
    cudaGetSymbolAddress((void**)&vlin,  g_vlin);
    cudaGetSymbolAddress((void**)&ahi,   g_a_hi);
    cudaGetSymbolAddress((void**)&alo,   g_a_lo);
    cudaGetSymbolAddress((void**)&whi,   g_w2_hi);
    cudaGetSymbolAddress((void**)&wlo,   g_w2_lo);

    conv5_kernel<<<B_*C_, 256>>>(x, dwqh_w, dwqh_b, dwkh_w, dwkh_b,
                                 dwv_w, dwv_b, dwqw_w, dwqw_b, dwkw_w, dwkw_b);

    linear_rm4_kernel<<<dim3(16, 4, 4), 256>>>(fcqh_w, fcqh_b, fckh_w, fckh_b,
                                               fcqw_w, fcqw_b, fckw_w, fckw_b);

    attn_kernel<<<256, 256>>>(Bh, Bw);

    wconv_kernel<<<dim3(64, 2), 256>>>(fcv_w, fco_w);

    // v linear: transpose+convert conv_v, then tensor GEMM into g_vlin
    atrans_kernel<<<dim3(64, 4, 16), 256>>>(convv);
    hmma_linear_kernel<<<dim3(512, 2), 256>>>(ahi, alo, whi, wlo, fcv_b, vlin);

    e1_kernel<<<dim3(128, 16), 256>>>();
    e2_kernel<<<dim3(128, 16), 256>>>();

    // output linear: transpose+convert g_r, then tensor GEMM into d_out
    atrans_kernel<<<dim3(64, 4, 16), 256>>>(r);
    hmma_linear_kernel<<<dim3(512, 2), 256>>>(ahi, alo, whi + C_*HD_, wlo + C_*HD_,
                                              fco_b, (float*)d_out);
}

// round 7
// speedup vs baseline: 1.5318x; 1.0668x over previous
#include <cuda_runtime.h>
#include <cuda_bf16.h>
#include <cstdint>

#define B_  16
#define C_  256
#define S_  64
#define H_  8
#define D_  32
#define HD_ 256
#define P_  4096

// scratch (device globals; allocations are forbidden)
__device__ float g_convv[(size_t)B_*C_*P_];      // [b][c][p] channel-major
__device__ float g_pool[4][B_*S_*C_];            // [path][b*64+pos][c]
__device__ float g_qk[4][B_*S_*HD_];             // [path][b*64+pos][hd]
__device__ float g_attn[2][B_*H_*S_*S_];         // [axis][bh][i][j]
__device__ float g_vlin[(size_t)B_*P_*HD_];      // [b][p][hd]
__device__ float g_M[(size_t)B_*H_*D_*S_*S_];    // [bh][dv][i][w]
__device__ float g_r[(size_t)B_*HD_*P_];         // [b][hd][p]
__device__ __nv_bfloat16 g_a_hi[(size_t)B_*P_*HD_];  // token-major [b][p][k]
__device__ __nv_bfloat16 g_a_lo[(size_t)B_*P_*HD_];
__device__ __nv_bfloat16 g_w2_hi[2][C_*HD_];
__device__ __nv_bfloat16 g_w2_lo[2][C_*HD_];

// ---- packed f32x2 helpers ----------------------------------------------------
__device__ __forceinline__ unsigned long long pack2(float x, float y) {
    unsigned long long r;
    asm("mov.b64 %0, {%1, %2};" : "=l"(r) : "f"(x), "f"(y));
    return r;
}
__device__ __forceinline__ void fma2(unsigned long long& d, unsigned long long a,
                                     unsigned long long b) {
    asm("fma.rn.f32x2 %0, %1, %2, %0;" : "+l"(d) : "l"(a), "l"(b));
}
__device__ __forceinline__ float2 unpack2(unsigned long long v) {
    float2 f;
    asm("mov.b64 {%0, %1}, %2;" : "=f"(f.x), "=f"(f.y) : "l"(v));
    return f;
}

// ---- warp-mma helpers ----------------------------------------------------------
__device__ __forceinline__ uint32_t smem_u32(const void* p) {
    uint32_t a;
    asm("{ .reg .u64 t; cvta.to.shared.u64 t, %1; cvt.u32.u64 %0, t; }" : "=r"(a) : "l"(p));
    return a;
}
__device__ __forceinline__ void ldm_x4(uint32_t addr, uint32_t* r) {
    asm volatile("ldmatrix.sync.aligned.m8n8.x4.shared.b16 {%0,%1,%2,%3}, [%4];"
                 : "=r"(r[0]), "=r"(r[1]), "=r"(r[2]), "=r"(r[3]) : "r"(addr));
}
__device__ __forceinline__ void ldm_x2(uint32_t addr, uint32_t* r) {
    asm volatile("ldmatrix.sync.aligned.m8n8.x2.shared.b16 {%0,%1}, [%2];"
                 : "=r"(r[0]), "=r"(r[1]) : "r"(addr));
}
__device__ __forceinline__ void ldm_x2t(uint32_t addr, uint32_t* r) {
    asm volatile("ldmatrix.sync.aligned.m8n8.x2.trans.shared.b16 {%0,%1}, [%2];"
                 : "=r"(r[0]), "=r"(r[1]) : "r"(addr));
}
__device__ __forceinline__ void mma_bf16(float* c, const uint32_t* a, const uint32_t* b) {
    asm volatile(
        "mma.sync.aligned.m16n8k16.row.col.f32.bf16.bf16.f32 "
        "{%0,%1,%2,%3}, {%4,%5,%6,%7}, {%8,%9}, {%0,%1,%2,%3};"
        : "+f"(c[0]), "+f"(c[1]), "+f"(c[2]), "+f"(c[3])
        : "r"(a[0]), "r"(a[1]), "r"(a[2]), "r"(a[3]), "r"(b[0]), "r"(b[1]));
}
__device__ __forceinline__ uint32_t bfpack2(float x, float y) {
    __nv_bfloat16 hx = __float2bfloat16(x), hy = __float2bfloat16(y);
    return ((uint32_t)__bfloat16_as_ushort(hy) << 16) | __bfloat16_as_ushort(hx);
}

// ---- kernel 1: fused 5x depthwise 3x3 conv + row/col means -----------------
__global__ void __launch_bounds__(256) conv5_kernel(
    const float* __restrict__ x,
    const float* __restrict__ w_qh, const float* __restrict__ b_qh,
    const float* __restrict__ w_kh, const float* __restrict__ b_kh,
    const float* __restrict__ w_v,  const float* __restrict__ b_v,
    const float* __restrict__ w_qw, const float* __restrict__ b_qw,
    const float* __restrict__ w_kw, const float* __restrict__ b_kw)
{
    __shared__ float tile[66*66];
    __shared__ float s_row[2][64];
    __shared__ float s_colbuf[2][256];

    int b = blockIdx.x >> 8;
    int c = blockIdx.x & 255;
    int tid = threadIdx.x;

    const float* xp = x + (size_t)(b*C_ + c) * P_;
    for (int idx = tid; idx < 66*66; idx += 256) {
        int r = idx / 66 - 1, cc = idx % 66 - 1;
        float v = 0.f;
        if ((unsigned)r < 64u && (unsigned)cc < 64u) v = xp[r*64 + cc];
        tile[idx] = v;
    }
    if (tid < 64) { s_row[0][tid] = 0.f; s_row[1][tid] = 0.f; }

    float wqh[9], wkh[9], wv[9], wqw[9], wkw[9];
    #pragma unroll
    for (int k = 0; k < 9; k++) {
        wqh[k] = w_qh[c*9+k]; wkh[k] = w_kh[c*9+k]; wv[k] = w_v[c*9+k];
        wqw[k] = w_qw[c*9+k]; wkw[k] = w_kw[c*9+k];
    }
    float bqh = b_qh[c], bkh = b_kh[c], bv = b_v[c], bqw = b_qw[c], bkw = b_kw[c];
    __syncthreads();

    float acc_qw = 0.f, acc_kw = 0.f;
    int col = tid & 63;
    float* outv = g_convv + (size_t)(b*C_ + c) * P_;

    #pragma unroll 4
    for (int it = 0; it < 16; it++) {
        int p = it*256 + tid;
        int r = p >> 6;
        float n[9];
        #pragma unroll
        for (int dr = 0; dr < 3; dr++)
            #pragma unroll
            for (int dc = 0; dc < 3; dc++)
                n[dr*3+dc] = tile[(r+dr)*66 + col + dc];
        float sv = bv, sqh = bqh, skh = bkh, sqw = bqw, skw = bkw;
        #pragma unroll
        for (int k = 0; k < 9; k++) {
            sv  += wv[k]  * n[k];
            sqh += wqh[k] * n[k];
            skh += wkh[k] * n[k];
            sqw += wqw[k] * n[k];
            skw += wkw[k] * n[k];
        }
        outv[p] = sv;
        acc_qw += sqw; acc_kw += skw;
        float rq = sqh, rk = skh;   // whole warp shares row r
        #pragma unroll
        for (int o = 16; o; o >>= 1) {
            rq += __shfl_down_sync(0xffffffffu, rq, o);
            rk += __shfl_down_sync(0xffffffffu, rk, o);
        }
        if ((tid & 31) == 0) { atomicAdd(&s_row[0][r], rq); atomicAdd(&s_row[1][r], rk); }
    }
    s_colbuf[0][tid] = acc_qw;
    s_colbuf[1][tid] = acc_kw;
    __syncthreads();

    if (tid < 64) {
        float cq = s_colbuf[0][tid] + s_colbuf[0][tid+64] + s_colbuf[0][tid+128] + s_colbuf[0][tid+192];
        float ck = s_colbuf[1][tid] + s_colbuf[1][tid+64] + s_colbuf[1][tid+128] + s_colbuf[1][tid+192];
        size_t o = (size_t)(b*64 + tid) * C_ + c;
        const float inv = 1.f / 64.f;
        g_pool[0][o] = s_row[0][tid] * inv;
        g_pool[1][o] = s_row[1][tid] * inv;
        g_pool[2][o] = cq * inv;
        g_pool[3][o] = ck * inv;
    }
}

// ---- kernel 2: batched small linear (4 paths), row-major A [M,K], W[N,K] ---
__global__ void __launch_bounds__(256) linear_rm4_kernel(
    const float* __restrict__ W0, const float* __restrict__ bias0,
    const float* __restrict__ W1, const float* __restrict__ bias1,
    const float* __restrict__ W2, const float* __restrict__ bias2,
    const float* __restrict__ W3, const float* __restrict__ bias3)
{
    __shared__ float As[16][64];
    __shared__ float Ws[16][64];
    int tid = threadIdx.x;
    int path = blockIdx.z;
    const float* A    = g_pool[path];
    const float* W    = path == 0 ? W0 : path == 1 ? W1 : path == 2 ? W2 : W3;
    const float* bias = path == 0 ? bias0 : path == 1 ? bias1 : path == 2 ? bias2 : bias3;
    float* out = g_qk[path];

    int m0 = blockIdx.x * 64, n0 = blockIdx.y * 64;
    int tx = tid & 15, ty = tid >> 4;
    int l_r = tid >> 2;
    int l_k = (tid & 3) * 4;
    float acc[4][4];
    #pragma unroll
    for (int i = 0; i < 4; i++)
        #pragma unroll
        for (int j = 0; j < 4; j++) acc[i][j] = 0.f;

    for (int k0 = 0; k0 < 256; k0 += 16) {
        float4 av = *(const float4*)(A + (size_t)(m0 + l_r) * 256 + k0 + l_k);
        float4 wv = *(const float4*)(W + (size_t)(n0 + l_r) * 256 + k0 + l_k);
        __syncthreads();
        As[l_k+0][l_r] = av.x; As[l_k+1][l_r] = av.y; As[l_k+2][l_r] = av.z; As[l_k+3][l_r] = av.w;
        Ws[l_k+0][l_r] = wv.x; Ws[l_k+1][l_r] = wv.y; Ws[l_k+2][l_r] = wv.z; Ws[l_k+3][l_r] = wv.w;
        __syncthreads();
        #pragma unroll
        for (int kk = 0; kk < 16; kk++) {
            float a[4], bb[4];
            *(float4*)a  = *(const float4*)&As[kk][ty*4];
            *(float4*)bb = *(const float4*)&Ws[kk][tx*4];
            #pragma unroll
            for (int i = 0; i < 4; i++)
                #pragma unroll
                for (int j = 0; j < 4; j++) acc[i][j] += a[i] * bb[j];
        }
    }
    float bs[4];
    #pragma unroll
    for (int j = 0; j < 4; j++) bs[j] = bias[n0 + tx*4 + j];
    #pragma unroll
    for (int i = 0; i < 4; i++) {
        float4 o;
        o.x = acc[i][0] + bs[0]; o.y = acc[i][1] + bs[1];
        o.z = acc[i][2] + bs[2]; o.w = acc[i][3] + bs[3];
        *(float4*)(out + (size_t)(m0 + ty*4 + i) * 256 + n0 + tx*4) = o;
    }
}

// ---- kernel 3: attention logits + softmax -----------------------------------
__global__ void __launch_bounds__(256) attn_kernel(const float* __restrict__ Bh,
                                                   const float* __restrict__ Bw)
{
    __shared__ float Qs[64*33];
    __shared__ float Ks[64*33];
    __shared__ float L[64*65];
    int tid = threadIdx.x;
    int path = blockIdx.x >> 7;
    int bh = blockIdx.x & 127;
    int b = bh >> 3, Hh = bh & 7;

    const float* qg = g_qk[path*2]   + (size_t)(b*64) * 256 + Hh*32;
    const float* kg = g_qk[path*2+1] + (size_t)(b*64) * 256 + Hh*32;
    const float* bias = (path ? Bw : Bh) + (size_t)Hh * 4096;

    for (int e = tid; e < 2048; e += 256) {
        int i = e >> 5, d = e & 31;
        Qs[i*33+d] = qg[(size_t)i*256 + d];
        Ks[i*33+d] = kg[(size_t)i*256 + d];
    }
    __syncthreads();
    const float scale = 0.17677669529663687f;
    for (int e = tid; e < 4096; e += 256) {
        int i = e >> 6, j = e & 63;
        float s = 0.f;
        #pragma unroll
        for (int d = 0; d < 32; d++) s += Qs[i*33+d] * Ks[j*33+d];
        L[i*65+j] = s * scale + bias[i*64 + j];
    }
    __syncthreads();
    int warp = tid >> 5, lane = tid & 31;
    float* outp = g_attn[path] + (size_t)bh * 4096;
    for (int r = warp; r < 64; r += 8) {
        float v0 = L[r*65 + lane], v1 = L[r*65 + 32 + lane];
        float mx = fmaxf(v0, v1);
        #pragma unroll
        for (int o = 16; o; o >>= 1) mx = fmaxf(mx, __shfl_xor_sync(0xffffffffu, mx, o));
        float e0 = __expf(v0 - mx), e1 = __expf(v1 - mx);
        float s = e0 + e1;
        #pragma unroll
        for (int o = 16; o; o >>= 1) s += __shfl_xor_sync(0xffffffffu, s, o);
        float inv = 1.f / s;
        outp[r*64 + lane]      = e0 * inv;
        outp[r*64 + 32 + lane] = e1 * inv;
    }
}

// ---- weight convert: fp32 [n][k] -> bf16 hi/lo --------------------------------
__global__ void __launch_bounds__(256) wconv_kernel(const float* __restrict__ Wv,
                                                    const float* __restrict__ Wo)
{
    int which = blockIdx.y;
    const float* src = which ? Wo : Wv;
    __nv_bfloat16* hi = g_w2_hi[which];
    __nv_bfloat16* lo = g_w2_lo[which];
    int idx = (blockIdx.x * 256 + threadIdx.x) * 4;
    float4 v = *(const float4*)(src + idx);
    __nv_bfloat16 h0 = __float2bfloat16(v.x), h1 = __float2bfloat16(v.y);
    __nv_bfloat16 h2 = __float2bfloat16(v.z), h3 = __float2bfloat16(v.w);
    __nv_bfloat16 l0 = __float2bfloat16(v.x - __bfloat162float(h0));
    __nv_bfloat16 l1 = __float2bfloat16(v.y - __bfloat162float(h1));
    __nv_bfloat16 l2 = __float2bfloat16(v.z - __bfloat162float(h2));
    __nv_bfloat16 l3 = __float2bfloat16(v.w - __bfloat162float(h3));
    uint32_t uh0 = ((uint32_t)__bfloat16_as_ushort(h1) << 16) | __bfloat16_as_ushort(h0);
    uint32_t uh1 = ((uint32_t)__bfloat16_as_ushort(h3) << 16) | __bfloat16_as_ushort(h2);
    uint32_t ul0 = ((uint32_t)__bfloat16_as_ushort(l1) << 16) | __bfloat16_as_ushort(l0);
    uint32_t ul1 = ((uint32_t)__bfloat16_as_ushort(l3) << 16) | __bfloat16_as_ushort(l2);
    *(uint2*)(hi + idx) = make_uint2(uh0, uh1);
    *(uint2*)(lo + idx) = make_uint2(ul0, ul1);
}

// ---- activation transpose+convert: fp32 [b][k][p] -> bf16 [b][p][k] hi/lo ----
__global__ void __launch_bounds__(256) atrans_kernel(const float* __restrict__ src)
{
    __shared__ float ts[64][65];
    int tid = threadIdx.x;
    int b = blockIdx.z, k0 = blockIdx.y * 64, p0 = blockIdx.x * 64;
    const float* s = src + ((size_t)(b*256 + k0)) * P_ + p0;
    int pq = (tid & 15) * 4, kr = tid >> 4;
    #pragma unroll
    for (int i = 0; i < 4; i++) {
        int k = kr + 16*i;
        float4 v = *(const float4*)(s + (size_t)k * P_ + pq);
        ts[k][pq+0] = v.x; ts[k][pq+1] = v.y; ts[k][pq+2] = v.z; ts[k][pq+3] = v.w;
    }
    __syncthreads();
    int kq = (tid & 15) * 4, pr = tid >> 4;
    #pragma unroll
    for (int i = 0; i < 4; i++) {
        int p = pr + 16*i;
        float a0 = ts[kq+0][p], a1 = ts[kq+1][p], a2 = ts[kq+2][p], a3 = ts[kq+3][p];
        __nv_bfloat16 h0 = __float2bfloat16(a0), h1 = __float2bfloat16(a1);
        __nv_bfloat16 h2 = __float2bfloat16(a2), h3 = __float2bfloat16(a3);
        __nv_bfloat16 l0 = __float2bfloat16(a0 - __bfloat162float(h0));
        __nv_bfloat16 l1 = __float2bfloat16(a1 - __bfloat162float(h1));
        __nv_bfloat16 l2 = __float2bfloat16(a2 - __bfloat162float(h2));
        __nv_bfloat16 l3 = __float2bfloat16(a3 - __bfloat162float(h3));
        size_t o = ((size_t)(b*P_ + p0 + p)) * 256 + k0 + kq;
        uint32_t uh0 = ((uint32_t)__bfloat16_as_ushort(h1) << 16) | __bfloat16_as_ushort(h0);
        uint32_t uh1 = ((uint32_t)__bfloat16_as_ushort(h3) << 16) | __bfloat16_as_ushort(h2);
        uint32_t ul0 = ((uint32_t)__bfloat16_as_ushort(l1) << 16) | __bfloat16_as_ushort(l0);
        uint32_t ul1 = ((uint32_t)__bfloat16_as_ushort(l3) << 16) | __bfloat16_as_ushort(l2);
        *(uint2*)(g_a_hi + o) = make_uint2(uh0, uh1);
        *(uint2*)(g_a_lo + o) = make_uint2(ul0, ul1);
    }
}

// ---- hmma_linear: mma.sync bf16 split GEMM ----------------------------------
__global__ void __launch_bounds__(256) hmma_linear_kernel(
    const __nv_bfloat16* __restrict__ aH, const __nv_bfloat16* __restrict__ aL,
    const __nv_bfloat16* __restrict__ wH, const __nv_bfloat16* __restrict__ wL,
    const float* __restrict__ bias, float* __restrict__ out)
{
    __shared__ __align__(16) __nv_bfloat16 sAH[128][40];
    __shared__ __align__(16) __nv_bfloat16 sAL[128][40];
    __shared__ __align__(16) __nv_bfloat16 sWH[128][40];
    __shared__ __align__(16) __nv_bfloat16 sWL[128][40];

    int tid = threadIdx.x, lane = tid & 31, wid = tid >> 5;
    int warp_m = wid >> 2, warp_n = wid & 3;
    int bm = blockIdx.x, n0 = blockIdx.y * 128;

    float acc[4][4][4];
    #pragma unroll
    for (int i = 0; i < 4; i++)
        #pragma unroll
        for (int j = 0; j < 4; j++)
            #pragma unroll
            for (int q = 0; q < 4; q++) acc[i][j][q] = 0.f;

    uint32_t bAH = smem_u32(sAH), bAL = smem_u32(sAL);
    uint32_t bWH = smem_u32(sWH), bWL = smem_u32(sWL);
    int arow = warp_m*64 + (lane & 15);
    int acol = (lane >> 4)*8;
    int brow = warp_n*32 + (lane & 7);
    int bcol = ((lane >> 3) & 1)*8;

    const size_t abase = ((size_t)bm * 128) * 256;
    const size_t wbase = ((size_t)n0) * 256;

    #pragma unroll 1
    for (int kc = 0; kc < 8; ++kc) {
        int k0 = kc * 32;
        #pragma unroll
        for (int q = 0; q < 2; ++q) {
            int u = q*256 + tid;
            int r = u >> 2, c = (u & 3) * 8;
            size_t ga = abase + (size_t)r*256 + k0 + c;
            size_t gw = wbase + (size_t)r*256 + k0 + c;
            *(uint4*)&sAH[r][c] = *(const uint4*)(aH + ga);
            *(uint4*)&sAL[r][c] = *(const uint4*)(aL + ga);
            *(uint4*)&sWH[r][c] = *(const uint4*)(wH + gw);
            *(uint4*)&sWL[r][c] = *(const uint4*)(wL + gw);
        }
        __syncthreads();
        #pragma unroll
        for (int s = 0; s < 2; ++s) {
            uint32_t ah[4][4], al[4][4];
            int colA = s*16 + acol;
            #pragma unroll
            for (int mt = 0; mt < 4; ++mt) {
                uint32_t off = (uint32_t)(((arow + mt*16)*40 + colA) * 2);
                ldm_x4(bAH + off, ah[mt]);
                ldm_x4(bAL + off, al[mt]);
            }
            int colB = s*16 + bcol;
            #pragma unroll
            for (int nt = 0; nt < 4; ++nt) {
                uint32_t off = (uint32_t)(((brow + nt*8)*40 + colB) * 2);
                uint32_t wh2[2], wl2[2];
                ldm_x2(bWH + off, wh2);
                ldm_x2(bWL + off, wl2);
                #pragma unroll
                for (int mt = 0; mt < 4; ++mt) {
                    mma_bf16(acc[mt][nt], ah[mt], wh2);
                    mma_bf16(acc[mt][nt], ah[mt], wl2);
                    mma_bf16(acc[mt][nt], al[mt], wh2);
                }
            }
        }
        __syncthreads();
    }

    int g = lane >> 2, t = lane & 3;
    #pragma unroll
    for (int nt = 0; nt < 4; ++nt) {
        int col = n0 + warp_n*32 + nt*8 + 2*t;
        float2 bv = *(const float2*)(bias + col);
        #pragma unroll
        for (int mt = 0; mt < 4; ++mt) {
            size_t row = (size_t)bm*128 + warp_m*64 + mt*16 + g;
            float2 o0, o1;
            o0.x = acc[mt][nt][0] + bv.x; o0.y = acc[mt][nt][1] + bv.y;
            o1.x = acc[mt][nt][2] + bv.x; o1.y = acc[mt][nt][3] + bv.y;
            *(float2*)(out + row*256 + col) = o0;
            *(float2*)(out + (row + 8)*256 + col) = o1;
        }
    }
}

// ---- kernel 5: M[bh][dv][i][w] = sum_ii attn_h[i][ii] * v[(ii,w),hd] --------
__global__ void __launch_bounds__(256) e1_kernel()
{
    __shared__ float As[64*64];
    __shared__ float Vs[64*128];   // [ii][dv*16 + w]
    int tid = threadIdx.x;
    int bh = blockIdx.x;
    int b = bh >> 3, Hh = bh & 7;
    int dt = blockIdx.y >> 2;
    int wt = blockIdx.y & 3;

    const float* Ag = g_attn[0] + (size_t)bh * 4096;
    for (int e = tid; e < 4096; e += 256) As[e] = Ag[e];

    const float* Vg = g_vlin + (size_t)b * P_ * 256 + Hh*32 + dt*8;
    for (int e = tid; e < 8192; e += 256) {
        int dv = e & 7, w = (e >> 3) & 15, ii = e >> 7;
        Vs[ii*128 + dv*16 + w] = Vg[(size_t)(ii*64 + wt*16 + w) * 256 + dv];
    }
    __syncthreads();

    int ty = tid >> 5;
    int tx = tid & 31;
    int dv = tx & 7, wg = tx >> 3;
    unsigned long long acc2[8][2];
    #pragma unroll
    for (int r = 0; r < 8; r++) { acc2[r][0] = 0ULL; acc2[r][1] = 0ULL; }

    #pragma unroll 2
    for (int ii = 0; ii < 64; ii++) {
        ulonglong2 vv = *(const ulonglong2*)&Vs[ii*128 + dv*16 + wg*4];
        #pragma unroll
        for (int r = 0; r < 8; r++) {
            float a = As[(ty*8 + r)*64 + ii];
            unsigned long long a2 = pack2(a, a);
            fma2(acc2[r][0], a2, vv.x);
            fma2(acc2[r][1], a2, vv.y);
        }
    }
    float* Mb = g_M + (size_t)bh * (D_*S_*S_);
    #pragma unroll
    for (int r = 0; r < 8; r++) {
        int i = ty*8 + r;
        float2 lo = unpack2(acc2[r][0]), hi = unpack2(acc2[r][1]);
        float4 o; o.x = lo.x; o.y = lo.y; o.z = hi.x; o.w = hi.y;
        *(float4*)&Mb[(size_t)(dt*8 + dv)*4096 + i*64 + wt*16 + wg*4] = o;
    }
}

// ---- kernel 6: e2 on tensor pipe. Per bh: C[(dv,i)][j] = sum_w M[(dv,i)][w]*attn_w[w][j]
// A = g_M rows (k=w contiguous); B = attn_w via ldmatrix.trans; split bf16, 3 terms.
// dyn smem: sAH[128][72], sAL[128][72], sBH[64][72], sBL[64][72]  (55296 B)
__global__ void __launch_bounds__(256) e2_hmma_kernel()
{
    extern __shared__ __align__(16) char e2s[];
    __nv_bfloat16* sAH = (__nv_bfloat16*)(e2s);
    __nv_bfloat16* sAL = (__nv_bfloat16*)(e2s + 18432);
    __nv_bfloat16* sBH = (__nv_bfloat16*)(e2s + 36864);
    __nv_bfloat16* sBL = (__nv_bfloat16*)(e2s + 46080);

    int tid = threadIdx.x, lane = tid & 31, wid = tid >> 5;
    int bh = blockIdx.x, mt = blockIdx.y;
    int b = bh >> 3, Hh = bh & 7;

    // B = attn_w[bh] 64x64 fp32 -> bf16 hi/lo, natural [w][j] (k-major rows)
    const float* Bg = g_attn[1] + (size_t)bh * 4096;
    #pragma unroll
    for (int q = 0; q < 4; ++q) {
        int idx = (q*256 + tid)*4;
        int w = idx >> 6, j = idx & 63;
        float4 v = *(const float4*)(Bg + idx);
        __nv_bfloat16 h0 = __float2bfloat16(v.x), h1 = __float2bfloat16(v.y);
        __nv_bfloat16 h2 = __float2bfloat16(v.z), h3 = __float2bfloat16(v.w);
        uint32_t hA = ((uint32_t)__bfloat16_as_ushort(h1) << 16) | __bfloat16_as_ushort(h0);
        uint32_t hB = ((uint32_t)__bfloat16_as_ushort(h3) << 16) | __bfloat16_as_ushort(h2);
        uint32_t lA = bfpack2(v.x - __bfloat162float(h0), v.y - __bfloat162float(h1));
        uint32_t lB = bfpack2(v.z - __bfloat162float(h2), v.w - __bfloat162float(h3));
        *(uint2*)&sBH[w*72 + j] = make_uint2(hA, hB);
        *(uint2*)&sBL[w*72 + j] = make_uint2(lA, lB);
    }
    // A = g_M[bh] rows mt*128..+127, k=64 contiguous
    const float* Ag = g_M + (size_t)bh * 131072 + (size_t)mt * 8192;
    #pragma unroll
    for (int q = 0; q < 8; ++q) {
        int idx = (q*256 + tid)*4;
        int m = idx >> 6, k = idx & 63;
        float4 v = *(const float4*)(Ag + idx);
        __nv_bfloat16 h0 = __float2bfloat16(v.x), h1 = __float2bfloat16(v.y);
        __nv_bfloat16 h2 = __float2bfloat16(v.z), h3 = __float2bfloat16(v.w);
        uint32_t hA = ((uint32_t)__bfloat16_as_ushort(h1) << 16) | __bfloat16_as_ushort(h0);
        uint32_t hB = ((uint32_t)__bfloat16_as_ushort(h3) << 16) | __bfloat16_as_ushort(h2);
        uint32_t lA = bfpack2(v.x - __bfloat162float(h0), v.y - __bfloat162float(h1));
        uint32_t lB = bfpack2(v.z - __bfloat162float(h2), v.w - __bfloat162float(h3));
        *(uint2*)&sAH[m*72 + k] = make_uint2(hA, hB);
        *(uint2*)&sAL[m*72 + k] = make_uint2(lA, lB);
    }
    __syncthreads();

    float acc[8][4];
    #pragma unroll
    for (int nt = 0; nt < 8; ++nt)
        #pragma unroll
        for (int q = 0; q < 4; ++q) acc[nt][q] = 0.f;

    uint32_t bAH = smem_u32(sAH), bAL = smem_u32(sAL);
    uint32_t bBH = smem_u32(sBH), bBL = smem_u32(sBL);
    int arow = wid*16 + (lane & 15);
    int acol = (lane >> 4)*8;
    int brow = lane & 15;   // lanes 0..15 supply ldmatrix.x2 addresses

    #pragma unroll
    for (int ks = 0; ks < 4; ++ks) {
        uint32_t ah[4], al[4];
        uint32_t offA = (uint32_t)((arow*72 + ks*16 + acol) * 2);
        ldm_x4(bAH + offA, ah);
        ldm_x4(bAL + offA, al);
        uint32_t offB = (uint32_t)(((ks*16 + brow)*72) * 2);
        #pragma unroll
        for (int nt = 0; nt < 8; ++nt) {
            uint32_t bhf[2], blf[2];
            ldm_x2t(bBH + offB + nt*16, bhf);
            ldm_x2t(bBL + offB + nt*16, blf);
            mma_bf16(acc[nt], ah, bhf);
            mma_bf16(acc[nt], ah, blf);
            mma_bf16(acc[nt], al, bhf);
        }
    }

    int g = lane >> 2, t = lane & 3;
    int m0 = mt*128 + wid*16 + g;
    int m1 = m0 + 8;
    #pragma unroll
    for (int nt = 0; nt < 8; ++nt) {
        int j = nt*8 + 2*t;
        int dv0 = m0 >> 6, i0 = m0 & 63;
        int dv1 = m1 >> 6, i1 = m1 & 63;
        float2 o0; o0.x = acc[nt][0]; o0.y = acc[nt][1];
        float2 o1; o1.x = acc[nt][2]; o1.y = acc[nt][3];
        *(float2*)(g_r + ((size_t)(b*256 + Hh*32 + dv0))*P_ + i0*64 + j) = o0;
        *(float2*)(g_r + ((size_t)(b*256 + Hh*32 + dv1))*P_ + i1*64 + j) = o1;
    }
}

// ---- host launcher ----------------------------------------------------------
extern "C" void kernel_launch(void* const* d_in, const int* in_sizes, int n_in,
                              void* d_out, int out_size)
{
    const float* x = (const float*)d_in[0];
    const float* dwqh_w = (const float*)d_in[1];  const float* dwqh_b = (const float*)d_in[2];
    const float* fcqh_w = (const float*)d_in[3];  const float* fcqh_b = (const float*)d_in[4];
    const float* dwkh_w = (const float*)d_in[5];  const float* dwkh_b = (const float*)d_in[6];
    const float* fckh_w = (const float*)d_in[7];  const float* fckh_b = (const float*)d_in[8];
    const float* Bh     = (const float*)d_in[9];
    const float* dwv_w  = (const float*)d_in[10]; const float* dwv_b  = (const float*)d_in[11];
    const float* fcv_w  = (const float*)d_in[12]; const float* fcv_b  = (const float*)d_in[13];
    const float* dwqw_w = (const float*)d_in[14]; const float* dwqw_b = (const float*)d_in[15];
    const float* fcqw_w = (const float*)d_in[16]; const float* fcqw_b = (const float*)d_in[17];
    const float* dwkw_w = (const float*)d_in[18]; const float* dwkw_b = (const float*)d_in[19];
    const float* fckw_w = (const float*)d_in[20]; const float* fckw_b = (const float*)d_in[21];
    const float* Bw     = (const float*)d_in[22];
    const float* fco_w  = (const float*)d_in[23]; const float* fco_b  = (const float*)d_in[24];

    float *convv, *r, *vlin;
    __nv_bfloat16 *ahi, *alo, *whi, *wlo;
    cudaGetSymbolAddress((void**)&convv, g_convv);
    cudaGetSymbolAddress((void**)&r,     g_r);
    cudaGetSymbolAddress((void**)&vlin,  g_vlin);
    cudaGetSymbolAddress((void**)&ahi,   g_a_hi);
    cudaGetSymbolAddress((void**)&alo,   g_a_lo);
    cudaGetSymbolAddress((void**)&whi,   g_w2_hi);
    cudaGetSymbolAddress((void**)&wlo,   g_w2_lo);

    cudaFuncSetAttribute(e2_hmma_kernel, cudaFuncAttributeMaxDynamicSharedMemorySize, 55296);

    conv5_kernel<<<B_*C_, 256>>>(x, dwqh_w, dwqh_b, dwkh_w, dwkh_b,
                                 dwv_w, dwv_b, dwqw_w, dwqw_b, dwkw_w, dwkw_b);

    linear_rm4_kernel<<<dim3(16, 4, 4), 256>>>(fcqh_w, fcqh_b, fckh_w, fckh_b,
                                               fcqw_w, fcqw_b, fckw_w, fckw_b);

    attn_kernel<<<256, 256>>>(Bh, Bw);

    wconv_kernel<<<dim3(64, 2), 256>>>(fcv_w, fco_w);

    // v linear: transpose+convert conv_v, then tensor GEMM into g_vlin
    atrans_kernel<<<dim3(64, 4, 16), 256>>>(convv);
    hmma_linear_kernel<<<dim3(512, 2), 256>>>(ahi, alo, whi, wlo, fcv_b, vlin);

    e1_kernel<<<dim3(128, 16), 256>>>();
    e2_hmma_kernel<<<dim3(128, 16), 256, 55296>>>();

    // output linear: transpose+convert g_r, then tensor GEMM into d_out
    atrans_kernel<<<dim3(64, 4, 16), 256>>>(r);
    hmma_linear_kernel<<<dim3(512, 2), 256>>>(ahi, alo, whi + C_*HD_, wlo + C_*HD_,
                                              fco_b, (float*)d_out);
}